// round 1
// baseline (speedup 1.0000x reference)
#include <cuda_runtime.h>

#define CC     64      // channels
#define NCOMP  13      // 1 + 3 + 9 Cartesian components
#define NPATHS 11
#define RR     8       // radial basis
#define HH     64      // MLP hidden
#define EPB    8       // edges per block in k_edge
#define MAXN   8000

// scratch: u = linear_up output, acc = scatter accumulator, layout [n][comp][c]
__device__ __align__(16) float g_u[MAXN * NCOMP * CC];
__device__ __align__(16) float g_acc[MAXN * NCOMP * CC];

__device__ __forceinline__ float silu(float x) {
    return x / (1.0f + __expf(-x));
}

// ---------------------------------------------------------------------------
__global__ void k_zero(int n4) {
    int i = blockIdx.x * blockDim.x + threadIdx.x;
    if (i < n4) reinterpret_cast<float4*>(g_acc)[i] = make_float4(0.f, 0.f, 0.f, 0.f);
}

// ---------------------------------------------------------------------------
// linear_up: u[n][comp][d] = sum_c t_comp[n][c] * W_l[c][d]
__global__ void __launch_bounds__(128) k_linear_up(
    const float* __restrict__ t0, const float* __restrict__ t1, const float* __restrict__ t2,
    const float* __restrict__ W0, const float* __restrict__ W1, const float* __restrict__ W2)
{
    __shared__ float s_t[NCOMP][CC];
    const int n   = blockIdx.x;
    const int tid = threadIdx.x;

    for (int idx = tid; idx < NCOMP * CC; idx += 128) {
        int comp = idx >> 6, c = idx & 63;
        float v;
        if (comp == 0)      v = t0[n * CC + c];
        else if (comp < 4)  v = t1[(n * CC + c) * 3 + (comp - 1)];
        else                v = t2[(n * CC + c) * 9 + (comp - 4)];
        s_t[comp][c] = v;
    }
    __syncthreads();

    for (int out = tid; out < NCOMP * CC; out += 128) {
        int comp = out >> 6, d = out & 63;
        const float* __restrict__ W = (comp == 0) ? W0 : ((comp < 4) ? W1 : W2);
        float acc = 0.f;
        #pragma unroll
        for (int c = 0; c < CC; c++)
            acc = fmaf(s_t[comp][c], __ldg(&W[c * CC + d]), acc);
        g_u[(n * NCOMP + comp) * CC + d] = acc;
    }
}

// ---------------------------------------------------------------------------
// Fused edge kernel: radial MLP + path weights + tensor product + atomic scatter.
// 128 threads handle EPB=8 edges. d = tid&63 (channel/col), g = tid>>6 (0/1).
__global__ void __launch_bounds__(128) k_edge(
    const float* __restrict__ a0g, const float* __restrict__ a1g, const float* __restrict__ a2g,
    const float* __restrict__ ef,  const float* __restrict__ cut,
    const float* __restrict__ Wr0, const float* __restrict__ Wr1,
    const float* __restrict__ Wr2, const float* __restrict__ Wr3,
    const int*   __restrict__ ei,  int E)
{
    __shared__ __align__(16) float s_h1[HH][EPB];   // ping
    __shared__ __align__(16) float s_h2[HH][EPB];   // pong
    __shared__ float s_f[EPB][RR];
    __shared__ float s_w[EPB][NPATHS][CC];
    __shared__ float s_a[EPB][16];                  // 13 used, padded
    __shared__ float s_cut[EPB];
    __shared__ int   s_src[EPB];
    __shared__ int   s_dst[EPB];

    const int tid = threadIdx.x;
    const int e0  = blockIdx.x * EPB;

    // --- load per-edge small data ---
    for (int idx = tid; idx < EPB * RR; idx += 128) {
        int e = idx >> 3, r = idx & 7;
        int ge = e0 + e; if (ge >= E) ge = E - 1;
        s_f[e][r] = ef[ge * RR + r];
    }
    for (int idx = tid; idx < EPB * 13; idx += 128) {
        int e = idx / 13, k = idx - e * 13;
        int ge = e0 + e; if (ge >= E) ge = E - 1;
        float v;
        if (k == 0)     v = a0g[ge];
        else if (k < 4) v = a1g[ge * 3 + (k - 1)];
        else            v = a2g[ge * 9 + (k - 4)];
        s_a[e][k] = v;
    }
    if (tid < EPB) {
        int ge = e0 + tid; if (ge >= E) ge = E - 1;
        s_cut[tid] = cut[ge];
        s_src[tid] = ei[ge];
        s_dst[tid] = ei[E + ge];
    }
    __syncthreads();

    const int d = tid & 63;
    const int g = tid >> 6;

    // --- h1 = silu(f @ Wr0): each thread does 4 edges, one column d ---
    #pragma unroll
    for (int el = 0; el < 4; el++) {
        int e = g * 4 + el;
        float acc = 0.f;
        #pragma unroll
        for (int r = 0; r < RR; r++)
            acc = fmaf(s_f[e][r], __ldg(&Wr0[r * HH + d]), acc);
        s_h1[d][e] = silu(acc);
    }
    __syncthreads();

    // --- h2 = silu(h1 @ Wr1) ---
    {
        float a0_ = 0.f, a1_ = 0.f, a2_ = 0.f, a3_ = 0.f;
        const int eb = g * 4;
        #pragma unroll 8
        for (int k = 0; k < HH; k++) {
            float wv = __ldg(&Wr1[k * HH + d]);
            a0_ = fmaf(s_h1[k][eb + 0], wv, a0_);
            a1_ = fmaf(s_h1[k][eb + 1], wv, a1_);
            a2_ = fmaf(s_h1[k][eb + 2], wv, a2_);
            a3_ = fmaf(s_h1[k][eb + 3], wv, a3_);
        }
        s_h2[d][eb + 0] = silu(a0_);
        s_h2[d][eb + 1] = silu(a1_);
        s_h2[d][eb + 2] = silu(a2_);
        s_h2[d][eb + 3] = silu(a3_);
    }
    __syncthreads();

    // --- h3 = silu(h2 @ Wr2) -> back into s_h1 ---
    {
        float a0_ = 0.f, a1_ = 0.f, a2_ = 0.f, a3_ = 0.f;
        const int eb = g * 4;
        #pragma unroll 8
        for (int k = 0; k < HH; k++) {
            float wv = __ldg(&Wr2[k * HH + d]);
            a0_ = fmaf(s_h2[k][eb + 0], wv, a0_);
            a1_ = fmaf(s_h2[k][eb + 1], wv, a1_);
            a2_ = fmaf(s_h2[k][eb + 2], wv, a2_);
            a3_ = fmaf(s_h2[k][eb + 3], wv, a3_);
        }
        s_h1[d][eb + 0] = silu(a0_);
        s_h1[d][eb + 1] = silu(a1_);
        s_h1[d][eb + 2] = silu(a2_);
        s_h1[d][eb + 3] = silu(a3_);
    }
    __syncthreads();

    // --- w[e][p][d] = (h3 @ Wr3)[e, p*64+d] * cutoff[e] ---
    // Each Wr3 value loaded once, FMA'd into 8 edge accumulators (amortize L1/LDG 8x).
    {
        float acc[6][EPB];
        #pragma unroll
        for (int pl = 0; pl < 6; pl++)
            #pragma unroll
            for (int e = 0; e < EPB; e++) acc[pl][e] = 0.f;

        #pragma unroll 2
        for (int k = 0; k < HH; k++) {
            const float4 hlo = *reinterpret_cast<const float4*>(&s_h1[k][0]);
            const float4 hhi = *reinterpret_cast<const float4*>(&s_h1[k][4]);
            const float h[8] = {hlo.x, hlo.y, hlo.z, hlo.w, hhi.x, hhi.y, hhi.z, hhi.w};
            const float* __restrict__ wrow = Wr3 + k * (NPATHS * CC) + d;
            #pragma unroll
            for (int pl = 0; pl < 6; pl++) {
                int p = g * 6 + pl;
                if (p < NPATHS) {
                    float wv = __ldg(wrow + p * CC);
                    #pragma unroll
                    for (int e = 0; e < EPB; e++)
                        acc[pl][e] = fmaf(h[e], wv, acc[pl][e]);
                }
            }
        }
        #pragma unroll
        for (int pl = 0; pl < 6; pl++) {
            int p = g * 6 + pl;
            if (p < NPATHS) {
                #pragma unroll
                for (int e = 0; e < EPB; e++)
                    s_w[e][p][d] = acc[pl][e] * s_cut[e];
            }
        }
    }
    __syncthreads();

    // --- tensor product + atomic scatter: thread = channel d, 4 edges ---
    for (int el = 0; el < 4; el++) {
        const int e = g * 4 + el;
        if (e0 + e >= E) continue;
        const int src = s_src[e];
        const float* __restrict__ up = &g_u[src * NCOMP * CC + d];
        const float s0 = up[0];
        float s1[3], s2[9];
        #pragma unroll
        for (int i = 0; i < 3; i++) s1[i] = up[(1 + i) * CC];
        #pragma unroll
        for (int q = 0; q < 9; q++) s2[q] = up[(4 + q) * CC];

        float av[13];
        #pragma unroll
        for (int k = 0; k < 13; k++) av[k] = s_a[e][k];
        const float a0v = av[0];
        const float* a1v = av + 1;
        const float* a2v = av + 4;

        float w[NPATHS];
        #pragma unroll
        for (int p = 0; p < NPATHS; p++) w[p] = s_w[e][p][d];

        // lout = 0
        float dot11 = a1v[0]*s1[0] + a1v[1]*s1[1] + a1v[2]*s1[2];
        float dot22 = 0.f;
        #pragma unroll
        for (int q = 0; q < 9; q++) dot22 = fmaf(a2v[q], s2[q], dot22);
        float o0 = w[0] * (a0v * s0) + w[1] * dot11 + w[2] * dot22;

        // lout = 1
        float o1[3];
        #pragma unroll
        for (int i = 0; i < 3; i++) {
            float m21 = 0.f, m12 = 0.f;
            #pragma unroll
            for (int j = 0; j < 3; j++) {
                m21 = fmaf(a2v[i*3 + j], s1[j], m21);       // a2 @ s1
                m12 = fmaf(a1v[j], s2[i*3 + j], m12);       // a1 . s2[i,:]
            }
            o1[i] = w[3]*(a1v[i]*s0) + w[4]*(a0v*s1[i]) + w[5]*m21 + w[6]*m12;
        }

        // lout = 2
        float o2[9];
        #pragma unroll
        for (int i = 0; i < 3; i++) {
            #pragma unroll
            for (int j = 0; j < 3; j++) {
                float mm = 0.f;
                #pragma unroll
                for (int kk = 0; kk < 3; kk++)
                    mm = fmaf(a2v[i*3 + kk], s2[kk*3 + j], mm);  // a2 @ s2
                o2[i*3 + j] = w[7]*(a1v[i]*s1[j]) + w[8]*(a2v[i*3+j]*s0)
                            + w[9]*(a0v*s2[i*3+j]) + w[10]*mm;
            }
        }

        float* __restrict__ ap = &g_acc[s_dst[e] * NCOMP * CC + d];
        atomicAdd(&ap[0], o0);
        #pragma unroll
        for (int i = 0; i < 3; i++) atomicAdd(&ap[(1 + i) * CC], o1[i]);
        #pragma unroll
        for (int q = 0; q < 9; q++) atomicAdd(&ap[(4 + q) * CC], o2[q]);
    }
}

// ---------------------------------------------------------------------------
// per-node: /avg_neighbors, apply D symmetrization, write concatenated output
__global__ void k_final(const float* __restrict__ D0, const float* __restrict__ D1,
                        const float* __restrict__ D2, float* __restrict__ out, int N)
{
    int idx = blockIdx.x * blockDim.x + threadIdx.x;
    if (idx >= N * CC) return;
    const int n = idx >> 6;
    const int c = idx & 63;
    const float inv = 1.0f / 32.0f;
    const float* __restrict__ ap = &g_acc[n * NCOMP * CC + c];

    float m0 = ap[0] * inv;
    float m1[3], m2[9];
    #pragma unroll
    for (int i = 0; i < 3; i++) m1[i] = ap[(1 + i) * CC] * inv;
    #pragma unroll
    for (int q = 0; q < 9; q++) m2[q] = ap[(4 + q) * CC] * inv;

    out[idx] = m0 * __ldg(&D0[0]);

    float* __restrict__ o1 = out + N * CC;
    #pragma unroll
    for (int j = 0; j < 3; j++) {
        float s = 0.f;
        #pragma unroll
        for (int i = 0; i < 3; i++) s = fmaf(m1[i], __ldg(&D1[i * 3 + j]), s);
        o1[idx * 3 + j] = s;
    }

    float* __restrict__ o2 = out + N * CC * 4;
    #pragma unroll
    for (int q = 0; q < 9; q++) {
        float s = 0.f;
        #pragma unroll
        for (int p = 0; p < 9; p++) s = fmaf(m2[p], __ldg(&D2[p * 9 + q]), s);
        o2[idx * 9 + q] = s;
    }
}

// ---------------------------------------------------------------------------
extern "C" void kernel_launch(void* const* d_in, const int* in_sizes, int n_in,
                              void* d_out, int out_size)
{
    const float* t0  = (const float*)d_in[0];
    const float* t1  = (const float*)d_in[1];
    const float* t2  = (const float*)d_in[2];
    const float* a0  = (const float*)d_in[3];
    const float* a1  = (const float*)d_in[4];
    const float* a2  = (const float*)d_in[5];
    const float* ef  = (const float*)d_in[6];
    const float* cut = (const float*)d_in[7];
    const float* W0  = (const float*)d_in[8];
    const float* W1  = (const float*)d_in[9];
    const float* W2  = (const float*)d_in[10];
    const float* Wr0 = (const float*)d_in[11];
    const float* Wr1 = (const float*)d_in[12];
    const float* Wr2 = (const float*)d_in[13];
    const float* Wr3 = (const float*)d_in[14];
    const float* D0  = (const float*)d_in[15];
    const float* D1  = (const float*)d_in[16];
    const float* D2  = (const float*)d_in[17];
    const int*   ei  = (const int*)d_in[18];

    const int N = in_sizes[0] / CC;   // 8000
    const int E = in_sizes[3];        // 256000
    float* out = (float*)d_out;

    const int n4 = (N * NCOMP * CC) / 4;
    k_zero<<<(n4 + 255) / 256, 256>>>(n4);
    k_linear_up<<<N, 128>>>(t0, t1, t2, W0, W1, W2);
    k_edge<<<(E + EPB - 1) / EPB, 128>>>(a0, a1, a2, ef, cut, Wr0, Wr1, Wr2, Wr3, ei, E);
    k_final<<<(N * CC + 255) / 256, 256>>>(D0, D1, D2, out, N);
}

// round 2
// speedup vs baseline: 1.7918x; 1.7918x over previous
#include <cuda_runtime.h>

#define CC     64
#define NCOMP  13
#define NPATHS 11
#define RR     8
#define HH     64
#define EPB    16
#define TPB    256
#define MAXN   8000

__device__ __align__(16) float g_u[MAXN * NCOMP * CC];
__device__ __align__(16) float g_acc[MAXN * NCOMP * CC];

typedef unsigned long long u64t;

__device__ __forceinline__ u64t pack2(float lo, float hi) {
    u64t r; asm("mov.b64 %0,{%1,%2};" : "=l"(r) : "f"(lo), "f"(hi)); return r;
}
__device__ __forceinline__ void unpack2(u64t v, float& lo, float& hi) {
    asm("mov.b64 {%0,%1},%2;" : "=f"(lo), "=f"(hi) : "l"(v));
}
__device__ __forceinline__ u64t fma2(u64t a, u64t b, u64t c) {
    u64t d; asm("fma.rn.f32x2 %0,%1,%2,%3;" : "=l"(d) : "l"(a), "l"(b), "l"(c)); return d;
}
__device__ __forceinline__ void red4(float* p, float x, float y, float z, float w) {
    asm volatile("red.global.add.v4.f32 [%0], {%1,%2,%3,%4};"
                 :: "l"(p), "f"(x), "f"(y), "f"(z), "f"(w) : "memory");
}
__device__ __forceinline__ float silu(float x) { return x / (1.0f + __expf(-x)); }

// ---------------------------------------------------------------------------
__global__ void k_zero(int n4) {
    int i = blockIdx.x * blockDim.x + threadIdx.x;
    if (i < n4) reinterpret_cast<float4*>(g_acc)[i] = make_float4(0.f, 0.f, 0.f, 0.f);
}

// ---------------------------------------------------------------------------
__global__ void __launch_bounds__(128) k_linear_up(
    const float* __restrict__ t0, const float* __restrict__ t1, const float* __restrict__ t2,
    const float* __restrict__ W0, const float* __restrict__ W1, const float* __restrict__ W2)
{
    __shared__ float s_t[NCOMP][CC];
    const int n   = blockIdx.x;
    const int tid = threadIdx.x;

    for (int idx = tid; idx < NCOMP * CC; idx += 128) {
        int comp = idx >> 6, c = idx & 63;
        float v;
        if (comp == 0)      v = t0[n * CC + c];
        else if (comp < 4)  v = t1[(n * CC + c) * 3 + (comp - 1)];
        else                v = t2[(n * CC + c) * 9 + (comp - 4)];
        s_t[comp][c] = v;
    }
    __syncthreads();

    for (int out = tid; out < NCOMP * CC; out += 128) {
        int comp = out >> 6, d = out & 63;
        const float* __restrict__ W = (comp == 0) ? W0 : ((comp < 4) ? W1 : W2);
        float acc = 0.f;
        #pragma unroll
        for (int c = 0; c < CC; c++)
            acc = fmaf(s_t[comp][c], __ldg(&W[c * CC + d]), acc);
        g_u[(n * NCOMP + comp) * CC + d] = acc;
    }
}

// ---------------------------------------------------------------------------
// Fused edge kernel. 256 threads, 16 edges per block.
// Stages 1-4 (radial MLP + Wr3 GEMM): thread = (d = tid&63, g = tid>>6),
// f32x2-packed pairs of edges. Stage 5 (tensor product + scatter):
// thread = (e = tid>>4, 4-channel quad = tid&15), red.v4 atomics.
__global__ void __launch_bounds__(TPB) k_edge(
    const float* __restrict__ a0g, const float* __restrict__ a1g, const float* __restrict__ a2g,
    const float* __restrict__ ef,  const float* __restrict__ cut,
    const float* __restrict__ Wr0, const float* __restrict__ Wr1,
    const float* __restrict__ Wr2, const float* __restrict__ Wr3,
    const int*   __restrict__ ei,  int E)
{
    extern __shared__ float sm[];
    float* s_h1 = sm;            // [HH][EPB]   1024
    float* s_h2 = sm + 1024;     // [HH][EPB]   1024
    float* s_f  = sm + 2048;     // [EPB][RR]    128
    float* s_a  = sm + 2176;     // [EPB][16]    256
    float* s_cut= sm + 2432;     // [EPB]         16
    float* s_w  = sm + 2448;     // [EPB][NPATHS][CC] 11264
    int*   s_src= (int*)(sm + 13712);
    int*   s_dst= s_src + EPB;

    const int tid = threadIdx.x;
    const int e0  = blockIdx.x * EPB;

    // ---- stage 0: load per-edge small data ----
    if (tid < EPB * RR) {
        int e = tid >> 3, r = tid & 7;
        int ge = e0 + e; if (ge >= E) ge = E - 1;
        s_f[e * RR + r] = ef[ge * RR + r];
    }
    if (tid < EPB * 13) {
        int e = tid / 13, k = tid - 13 * e;
        int ge = e0 + e; if (ge >= E) ge = E - 1;
        float v;
        if (k == 0)     v = a0g[ge];
        else if (k < 4) v = a1g[ge * 3 + (k - 1)];
        else            v = a2g[ge * 9 + (k - 4)];
        s_a[e * 16 + k] = v;
    }
    if (tid < EPB) {
        int ge = e0 + tid; if (ge >= E) ge = E - 1;
        s_cut[tid] = cut[ge];
        s_src[tid] = ei[ge];
        s_dst[tid] = ei[E + ge];
    }
    __syncthreads();

    const int d  = tid & 63;
    const int g  = tid >> 6;   // 0..3
    const int eb = g * 4;

    // ---- stage 1: h1 = silu(f @ Wr0) ----
    #pragma unroll
    for (int el = 0; el < 4; el++) {
        int e = eb + el;
        float acc = 0.f;
        #pragma unroll
        for (int r = 0; r < RR; r++)
            acc = fmaf(s_f[e * RR + r], __ldg(&Wr0[r * HH + d]), acc);
        s_h1[d * EPB + e] = silu(acc);
    }
    __syncthreads();

    // ---- stage 2: h2 = silu(h1 @ Wr1), f32x2 pairs ----
    {
        u64t acc0 = 0ull, acc1 = 0ull;
        #pragma unroll 8
        for (int k = 0; k < HH; k++) {
            float wv = __ldg(&Wr1[k * HH + d]);
            u64t wv2 = pack2(wv, wv);
            const u64t* h = (const u64t*)&s_h1[k * EPB + eb];
            acc0 = fma2(h[0], wv2, acc0);
            acc1 = fma2(h[1], wv2, acc1);
        }
        float x0, x1, x2, x3;
        unpack2(acc0, x0, x1); unpack2(acc1, x2, x3);
        s_h2[d * EPB + eb + 0] = silu(x0);
        s_h2[d * EPB + eb + 1] = silu(x1);
        s_h2[d * EPB + eb + 2] = silu(x2);
        s_h2[d * EPB + eb + 3] = silu(x3);
    }
    __syncthreads();

    // ---- stage 3: h3 = silu(h2 @ Wr2) -> s_h1 ----
    {
        u64t acc0 = 0ull, acc1 = 0ull;
        #pragma unroll 8
        for (int k = 0; k < HH; k++) {
            float wv = __ldg(&Wr2[k * HH + d]);
            u64t wv2 = pack2(wv, wv);
            const u64t* h = (const u64t*)&s_h2[k * EPB + eb];
            acc0 = fma2(h[0], wv2, acc0);
            acc1 = fma2(h[1], wv2, acc1);
        }
        float x0, x1, x2, x3;
        unpack2(acc0, x0, x1); unpack2(acc1, x2, x3);
        s_h1[d * EPB + eb + 0] = silu(x0);
        s_h1[d * EPB + eb + 1] = silu(x1);
        s_h1[d * EPB + eb + 2] = silu(x2);
        s_h1[d * EPB + eb + 3] = silu(x3);
    }
    __syncthreads();

    // ---- stage 4: w = (h3 @ Wr3) * cutoff ; group g owns paths 3g..3g+2 ----
    {
        u64t acc[3][8];
        #pragma unroll
        for (int j = 0; j < 3; j++)
            #pragma unroll
            for (int m = 0; m < 8; m++) acc[j][m] = 0ull;

        #pragma unroll 4
        for (int k = 0; k < HH; k++) {
            const ulonglong2* hq = (const ulonglong2*)&s_h1[k * EPB];
            ulonglong2 q0 = hq[0], q1 = hq[1], q2 = hq[2], q3 = hq[3];
            u64t h[8] = {q0.x, q0.y, q1.x, q1.y, q2.x, q2.y, q3.x, q3.y};
            const float* __restrict__ wr = Wr3 + k * (NPATHS * CC) + g * 3 * CC + d;
            #pragma unroll
            for (int j = 0; j < 3; j++) {
                if (g * 3 + j < NPATHS) {
                    float wv = __ldg(wr + j * CC);
                    u64t wv2 = pack2(wv, wv);
                    #pragma unroll
                    for (int m = 0; m < 8; m++)
                        acc[j][m] = fma2(h[m], wv2, acc[j][m]);
                }
            }
        }
        #pragma unroll
        for (int j = 0; j < 3; j++) {
            int p = g * 3 + j;
            if (p < NPATHS) {
                #pragma unroll
                for (int m = 0; m < 8; m++) {
                    float lo, hi; unpack2(acc[j][m], lo, hi);
                    s_w[((2 * m)     * NPATHS + p) * CC + d] = lo * s_cut[2 * m];
                    s_w[((2 * m + 1) * NPATHS + p) * CC + d] = hi * s_cut[2 * m + 1];
                }
            }
        }
    }
    __syncthreads();

    // ---- stage 5: tensor product + vectorized scatter ----
    {
        const int e  = tid >> 4;        // 0..15
        const int c0 = (tid & 15) * 4;  // channel quad
        if (e0 + e < E) {
            const int src = s_src[e];
            const float* __restrict__ up = &g_u[src * NCOMP * CC + c0];

            float s0[4], s1[3][4], s2[9][4];
            *(float4*)s0 = __ldg((const float4*)&up[0]);
            #pragma unroll
            for (int i = 0; i < 3; i++) *(float4*)s1[i] = __ldg((const float4*)&up[(1 + i) * CC]);
            #pragma unroll
            for (int q = 0; q < 9; q++) *(float4*)s2[q] = __ldg((const float4*)&up[(4 + q) * CC]);

            float av[13];
            #pragma unroll
            for (int k = 0; k < 13; k++) av[k] = s_a[e * 16 + k];
            const float  a0v = av[0];
            const float* a1v = av + 1;
            const float* a2v = av + 4;

            float w[NPATHS][4];
            #pragma unroll
            for (int p = 0; p < NPATHS; p++)
                *(float4*)w[p] = *(const float4*)&s_w[(e * NPATHS + p) * CC + c0];

            float* __restrict__ ap = &g_acc[s_dst[e] * NCOMP * CC + c0];

            // lout = 0
            float o0[4];
            #pragma unroll
            for (int c = 0; c < 4; c++) {
                float dot11 = a1v[0]*s1[0][c] + a1v[1]*s1[1][c] + a1v[2]*s1[2][c];
                float dot22 = 0.f;
                #pragma unroll
                for (int q = 0; q < 9; q++) dot22 = fmaf(a2v[q], s2[q][c], dot22);
                o0[c] = w[0][c] * (a0v * s0[c]) + w[1][c] * dot11 + w[2][c] * dot22;
            }
            red4(ap, o0[0], o0[1], o0[2], o0[3]);

            // lout = 1
            #pragma unroll
            for (int i = 0; i < 3; i++) {
                float o1[4];
                #pragma unroll
                for (int c = 0; c < 4; c++) {
                    float m21 = 0.f, m12 = 0.f;
                    #pragma unroll
                    for (int j = 0; j < 3; j++) {
                        m21 = fmaf(a2v[i*3 + j], s1[j][c], m21);
                        m12 = fmaf(a1v[j], s2[i*3 + j][c], m12);
                    }
                    o1[c] = w[3][c]*(a1v[i]*s0[c]) + w[4][c]*(a0v*s1[i][c])
                          + w[5][c]*m21 + w[6][c]*m12;
                }
                red4(ap + (1 + i) * CC, o1[0], o1[1], o1[2], o1[3]);
            }

            // lout = 2
            #pragma unroll
            for (int i = 0; i < 3; i++) {
                #pragma unroll
                for (int j = 0; j < 3; j++) {
                    float o2[4];
                    #pragma unroll
                    for (int c = 0; c < 4; c++) {
                        float mm = 0.f;
                        #pragma unroll
                        for (int kk = 0; kk < 3; kk++)
                            mm = fmaf(a2v[i*3 + kk], s2[kk*3 + j][c], mm);
                        o2[c] = w[7][c]*(a1v[i]*s1[j][c]) + w[8][c]*(a2v[i*3+j]*s0[c])
                              + w[9][c]*(a0v*s2[i*3+j][c]) + w[10][c]*mm;
                    }
                    red4(ap + (4 + i*3 + j) * CC, o2[0], o2[1], o2[2], o2[3]);
                }
            }
        }
    }
}

// ---------------------------------------------------------------------------
__global__ void k_final(const float* __restrict__ D0, const float* __restrict__ D1,
                        const float* __restrict__ D2, float* __restrict__ out, int N)
{
    int idx = blockIdx.x * blockDim.x + threadIdx.x;
    if (idx >= N * CC) return;
    const int n = idx >> 6;
    const int c = idx & 63;
    const float inv = 1.0f / 32.0f;
    const float* __restrict__ ap = &g_acc[n * NCOMP * CC + c];

    float m0 = ap[0] * inv;
    float m1[3], m2[9];
    #pragma unroll
    for (int i = 0; i < 3; i++) m1[i] = ap[(1 + i) * CC] * inv;
    #pragma unroll
    for (int q = 0; q < 9; q++) m2[q] = ap[(4 + q) * CC] * inv;

    out[idx] = m0 * __ldg(&D0[0]);

    float* __restrict__ o1 = out + N * CC;
    #pragma unroll
    for (int j = 0; j < 3; j++) {
        float s = 0.f;
        #pragma unroll
        for (int i = 0; i < 3; i++) s = fmaf(m1[i], __ldg(&D1[i * 3 + j]), s);
        o1[idx * 3 + j] = s;
    }

    float* __restrict__ o2 = out + N * CC * 4;
    #pragma unroll
    for (int q = 0; q < 9; q++) {
        float s = 0.f;
        #pragma unroll
        for (int p = 0; p < 9; p++) s = fmaf(m2[p], __ldg(&D2[p * 9 + q]), s);
        o2[idx * 9 + q] = s;
    }
}

// ---------------------------------------------------------------------------
extern "C" void kernel_launch(void* const* d_in, const int* in_sizes, int n_in,
                              void* d_out, int out_size)
{
    const float* t0  = (const float*)d_in[0];
    const float* t1  = (const float*)d_in[1];
    const float* t2  = (const float*)d_in[2];
    const float* a0  = (const float*)d_in[3];
    const float* a1  = (const float*)d_in[4];
    const float* a2  = (const float*)d_in[5];
    const float* ef  = (const float*)d_in[6];
    const float* cut = (const float*)d_in[7];
    const float* W0  = (const float*)d_in[8];
    const float* W1  = (const float*)d_in[9];
    const float* W2  = (const float*)d_in[10];
    const float* Wr0 = (const float*)d_in[11];
    const float* Wr1 = (const float*)d_in[12];
    const float* Wr2 = (const float*)d_in[13];
    const float* Wr3 = (const float*)d_in[14];
    const float* D0  = (const float*)d_in[15];
    const float* D1  = (const float*)d_in[16];
    const float* D2  = (const float*)d_in[17];
    const int*   ei  = (const int*)d_in[18];

    const int N = in_sizes[0] / CC;   // 8000
    const int E = in_sizes[3];        // 256000
    float* out = (float*)d_out;

    const size_t smem_edge = 13744 * sizeof(float);  // 54976 B
    cudaFuncSetAttribute(k_edge, cudaFuncAttributeMaxDynamicSharedMemorySize, (int)smem_edge);

    const int n4 = (N * NCOMP * CC) / 4;
    k_zero<<<(n4 + 255) / 256, 256>>>(n4);
    k_linear_up<<<N, 128>>>(t0, t1, t2, W0, W1, W2);
    k_edge<<<(E + EPB - 1) / EPB, TPB, smem_edge>>>(a0, a1, a2, ef, cut,
                                                   Wr0, Wr1, Wr2, Wr3, ei, E);
    k_final<<<(N * CC + 255) / 256, 256>>>(D0, D1, D2, out, N);
}

// round 4
// speedup vs baseline: 2.2351x; 1.2474x over previous
#include <cuda_runtime.h>
#include <cstdint>

#define CC     64
#define NCOMP  13
#define NPATHS 11
#define RR     8
#define HH     64
#define MAXN   8000
#define MAXE   256000

__device__ __align__(16) float g_u[MAXN * NCOMP * CC];
__device__ __align__(16) float g_acc[MAXN * NCOMP * CC];
__device__ __align__(16) float g_h[MAXE * HH];
__device__ __align__(16) float g_w[(size_t)MAXE * NPATHS * CC];

typedef unsigned long long u64t;

__device__ __forceinline__ u64t pack2(float lo, float hi) {
    u64t r; asm("mov.b64 %0,{%1,%2};" : "=l"(r) : "f"(lo), "f"(hi)); return r;
}
__device__ __forceinline__ void unpack2(u64t v, float& lo, float& hi) {
    asm("mov.b64 {%0,%1},%2;" : "=f"(lo), "=f"(hi) : "l"(v));
}
__device__ __forceinline__ u64t fma2(u64t a, u64t b, u64t c) {
    u64t d; asm("fma.rn.f32x2 %0,%1,%2,%3;" : "=l"(d) : "l"(a), "l"(b), "l"(c)); return d;
}
__device__ __forceinline__ void red4(float* p, float x, float y, float z, float w) {
    asm volatile("red.global.add.v4.f32 [%0], {%1,%2,%3,%4};"
                 :: "l"(p), "f"(x), "f"(y), "f"(z), "f"(w) : "memory");
}
__device__ __forceinline__ float silu(float x) { return x / (1.0f + __expf(-x)); }
__device__ __forceinline__ float cvt_tf32(float x) {
    uint32_t u; asm("cvt.rna.tf32.f32 %0, %1;" : "=r"(u) : "f"(x));
    return __uint_as_float(u);
}
__device__ __forceinline__ void mma_tf32(float& d0, float& d1, float& d2, float& d3,
                                         uint32_t a0, uint32_t a1, uint32_t a2, uint32_t a3,
                                         uint32_t b0, uint32_t b1) {
    asm volatile("mma.sync.aligned.m16n8k8.row.col.f32.tf32.tf32.f32 "
                 "{%0,%1,%2,%3}, {%4,%5,%6,%7}, {%8,%9}, {%0,%1,%2,%3};"
                 : "+f"(d0), "+f"(d1), "+f"(d2), "+f"(d3)
                 : "r"(a0), "r"(a1), "r"(a2), "r"(a3), "r"(b0), "r"(b1));
}

// ---------------------------------------------------------------------------
__global__ void k_zero(int n4) {
    int i = blockIdx.x * blockDim.x + threadIdx.x;
    if (i < n4) reinterpret_cast<float4*>(g_acc)[i] = make_float4(0.f, 0.f, 0.f, 0.f);
}

// ---------------------------------------------------------------------------
__global__ void __launch_bounds__(128) k_linear_up(
    const float* __restrict__ t0, const float* __restrict__ t1, const float* __restrict__ t2,
    const float* __restrict__ W0, const float* __restrict__ W1, const float* __restrict__ W2)
{
    __shared__ float s_t[NCOMP][CC];
    const int n = blockIdx.x, tid = threadIdx.x;
    for (int idx = tid; idx < NCOMP * CC; idx += 128) {
        int comp = idx >> 6, c = idx & 63;
        float v;
        if (comp == 0)      v = t0[n * CC + c];
        else if (comp < 4)  v = t1[(n * CC + c) * 3 + (comp - 1)];
        else                v = t2[(n * CC + c) * 9 + (comp - 4)];
        s_t[comp][c] = v;
    }
    __syncthreads();
    for (int out = tid; out < NCOMP * CC; out += 128) {
        int comp = out >> 6, d = out & 63;
        const float* __restrict__ W = (comp == 0) ? W0 : ((comp < 4) ? W1 : W2);
        float acc = 0.f;
        #pragma unroll
        for (int c = 0; c < CC; c++) acc = fmaf(s_t[comp][c], __ldg(&W[c * CC + d]), acc);
        g_u[(n * NCOMP + comp) * CC + d] = acc;
    }
}

// ---------------------------------------------------------------------------
// MLP: h3[e][d] = silu(silu(silu(f@Wr0)@Wr1)@Wr2), tf32-rounded, 64 edges/block
#define MLP_EPB 64
__global__ void __launch_bounds__(512) k_mlp(
    const float* __restrict__ ef, const float* __restrict__ Wr0,
    const float* __restrict__ Wr1, const float* __restrict__ Wr2, int E)
{
    __shared__ float s_f[MLP_EPB][RR];
    __shared__ float s_h1[HH][MLP_EPB + 2];
    __shared__ float s_h2[HH][MLP_EPB + 2];
    const int tid = threadIdx.x;
    const int e0  = blockIdx.x * MLP_EPB;
    {
        int e = tid >> 3, r = tid & 7;
        int ge = e0 + e; if (ge >= E) ge = E - 1;
        s_f[e][r] = ef[ge * RR + r];
    }
    __syncthreads();
    const int d = tid & 63, g = tid >> 6, eb = g * 8;

    #pragma unroll
    for (int el = 0; el < 8; el++) {
        float acc = 0.f;
        #pragma unroll
        for (int r = 0; r < RR; r++) acc = fmaf(s_f[eb + el][r], __ldg(&Wr0[r * HH + d]), acc);
        s_h1[d][eb + el] = silu(acc);
    }
    __syncthreads();
    {
        u64t a[4] = {0, 0, 0, 0};
        #pragma unroll 8
        for (int k = 0; k < HH; k++) {
            float wv = __ldg(&Wr1[k * HH + d]); u64t wv2 = pack2(wv, wv);
            const u64t* h = (const u64t*)&s_h1[k][eb];
            a[0] = fma2(h[0], wv2, a[0]); a[1] = fma2(h[1], wv2, a[1]);
            a[2] = fma2(h[2], wv2, a[2]); a[3] = fma2(h[3], wv2, a[3]);
        }
        #pragma unroll
        for (int m = 0; m < 4; m++) {
            float lo, hi; unpack2(a[m], lo, hi);
            s_h2[d][eb + 2*m] = silu(lo); s_h2[d][eb + 2*m + 1] = silu(hi);
        }
    }
    __syncthreads();
    {
        u64t a[4] = {0, 0, 0, 0};
        #pragma unroll 8
        for (int k = 0; k < HH; k++) {
            float wv = __ldg(&Wr2[k * HH + d]); u64t wv2 = pack2(wv, wv);
            const u64t* h = (const u64t*)&s_h2[k][eb];
            a[0] = fma2(h[0], wv2, a[0]); a[1] = fma2(h[1], wv2, a[1]);
            a[2] = fma2(h[2], wv2, a[2]); a[3] = fma2(h[3], wv2, a[3]);
        }
        #pragma unroll
        for (int m = 0; m < 4; m++) {
            float lo, hi; unpack2(a[m], lo, hi);
            s_h1[d][eb + 2*m]     = cvt_tf32(silu(lo));
            s_h1[d][eb + 2*m + 1] = cvt_tf32(silu(hi));
        }
    }
    __syncthreads();
    #pragma unroll
    for (int i = 0; i < 8; i++) {
        int flat = i * 512 + tid;
        int e = flat >> 6, dd = flat & 63;
        if (e0 + e < E) g_h[(size_t)(e0 + e) * HH + dd] = s_h1[dd][e];
    }
}

// ---------------------------------------------------------------------------
// tf32 mma.sync GEMM: w[e][p*64+c] = (h3[e,:] @ Wr3[:, p*64+c]) * cutoff[e]
// Block: 256 thr / 128 edges. Wr3 (64x704, pad 708) + h (128x64, pad 68) in smem.
// Warp w owns rows [w*16, w*16+16); loops 88 n8-tiles x 8 k8-steps.
#define GEPB   128
#define HPAD   68     // 68 % 32 == 4 -> conflict-free A loads
#define WPAD   708    // 708 % 32 == 4 -> conflict-free B loads
#define SM_H   0                               // 128*68*4   = 34816
#define SM_W   34816                           // 64*708*4   = 181248
#define SM_CUT 216064                          // 128*4      = 512
#define SM_TOT 216576

__global__ void __launch_bounds__(256) k_wgemm(
    const float* __restrict__ Wr3, const float* __restrict__ cut, int E)
{
    extern __shared__ char smem[];
    float* s_h   = (float*)(smem + SM_H);
    float* s_wr  = (float*)(smem + SM_W);
    float* s_cut = (float*)(smem + SM_CUT);

    const int tid = threadIdx.x;
    const int e0  = blockIdx.x * GEPB;

    // stage h tile: 128 rows x 64 cols (already tf32-rounded by k_mlp)
    #pragma unroll
    for (int i = 0; i < 8; i++) {
        int flat = i * 256 + tid;            // 0..2047
        int row = flat >> 4, c4 = flat & 15;
        int ge = e0 + row; if (ge >= E) ge = E - 1;
        float4 v = *(const float4*)&g_h[(size_t)ge * HH + c4 * 4];
        *(float4*)&s_h[row * HPAD + c4 * 4] = v;
    }
    // stage Wr3: 64 rows(k) x 704 cols, tf32-rounded
    #pragma unroll 4
    for (int i = 0; i < 44; i++) {
        int flat = i * 256 + tid;            // 0..11263
        int row = flat / 176, q = flat % 176;
        float4 v = *(const float4*)&Wr3[row * (NPATHS * CC) + q * 4];
        v.x = cvt_tf32(v.x); v.y = cvt_tf32(v.y); v.z = cvt_tf32(v.z); v.w = cvt_tf32(v.w);
        *(float4*)&s_wr[row * WPAD + q * 4] = v;
    }
    if (tid < GEPB) {
        int ge = e0 + tid; if (ge >= E) ge = E - 1;
        s_cut[tid] = cut[ge];
    }
    __syncthreads();

    const int wid  = tid >> 5, lane = tid & 31;
    const int gid  = lane >> 2, tig = lane & 3;
    const int m0   = wid * 16;
    const int ra   = m0 + gid;       // rows for d0/d1
    const int rb   = m0 + gid + 8;   // rows for d2/d3

    // preload A fragments for all 8 k-steps
    uint32_t a[8][4];
    const uint32_t* hA = (const uint32_t*)s_h;
    #pragma unroll
    for (int ks = 0; ks < 8; ks++) {
        a[ks][0] = hA[ra * HPAD + ks * 8 + tig];
        a[ks][1] = hA[rb * HPAD + ks * 8 + tig];
        a[ks][2] = hA[ra * HPAD + ks * 8 + tig + 4];
        a[ks][3] = hA[rb * HPAD + ks * 8 + tig + 4];
    }
    const float cut_a = s_cut[ra];
    const float cut_b = s_cut[rb];
    const bool  ok_a  = (e0 + ra) < E;
    const bool  ok_b  = (e0 + rb) < E;
    const uint32_t* wB = (const uint32_t*)s_wr;

    #pragma unroll 2
    for (int j = 0; j < 88; j++) {
        const int nb = j * 8;
        float d0 = 0.f, d1 = 0.f, d2 = 0.f, d3 = 0.f;
        #pragma unroll
        for (int ks = 0; ks < 8; ks++) {
            uint32_t b0 = wB[(ks * 8 + tig)     * WPAD + nb + gid];
            uint32_t b1 = wB[(ks * 8 + tig + 4) * WPAD + nb + gid];
            mma_tf32(d0, d1, d2, d3, a[ks][0], a[ks][1], a[ks][2], a[ks][3], b0, b1);
        }
        const int c = nb + tig * 2;          // col pair (c, c+1), same path block
        const int p = c >> 6, cc = c & 63;
        if (ok_a) {
            float2 v = make_float2(d0 * cut_a, d1 * cut_a);
            *(float2*)&g_w[((size_t)(e0 + ra) * NPATHS + p) * CC + cc] = v;
        }
        if (ok_b) {
            float2 v = make_float2(d2 * cut_b, d3 * cut_b);
            *(float2*)&g_w[((size_t)(e0 + rb) * NPATHS + p) * CC + cc] = v;
        }
    }
}

// ---------------------------------------------------------------------------
// TP + scatter: 16 edges/block, thread = (edge, channel-quad)
#define TEPB 16
__global__ void __launch_bounds__(256) k_tp(
    const float* __restrict__ a0g, const float* __restrict__ a1g, const float* __restrict__ a2g,
    const int* __restrict__ ei, int E)
{
    __shared__ float s_a[TEPB][16];
    const int tid = threadIdx.x;
    const int e0  = blockIdx.x * TEPB;

    if (tid < TEPB * 13) {
        int e = tid / 13, k = tid - 13 * e;
        int ge = e0 + e; if (ge >= E) ge = E - 1;
        float v;
        if (k == 0)     v = a0g[ge];
        else if (k < 4) v = a1g[ge * 3 + (k - 1)];
        else            v = a2g[ge * 9 + (k - 4)];
        s_a[e][k] = v;
    }
    __syncthreads();

    const int e  = tid >> 4;
    const int c0 = (tid & 15) * 4;
    const int ge = e0 + e;
    if (ge >= E) return;
    const int src = __ldg(&ei[ge]);
    const int dst = __ldg(&ei[E + ge]);

    const float* __restrict__ up = &g_u[src * NCOMP * CC + c0];
    float s0[4], s1[3][4], s2[9][4];
    *(float4*)s0 = __ldg((const float4*)&up[0]);
    #pragma unroll
    for (int i = 0; i < 3; i++) *(float4*)s1[i] = __ldg((const float4*)&up[(1 + i) * CC]);
    #pragma unroll
    for (int q = 0; q < 9; q++) *(float4*)s2[q] = __ldg((const float4*)&up[(4 + q) * CC]);

    float av[13];
    #pragma unroll
    for (int k = 0; k < 13; k++) av[k] = s_a[e][k];
    const float  a0v = av[0];
    const float* a1v = av + 1;
    const float* a2v = av + 4;

    float w[NPATHS][4];
    #pragma unroll
    for (int p = 0; p < NPATHS; p++)
        *(float4*)w[p] = __ldg((const float4*)&g_w[((size_t)ge * NPATHS + p) * CC + c0]);

    float* __restrict__ ap = &g_acc[dst * NCOMP * CC + c0];

    float o0[4];
    #pragma unroll
    for (int c = 0; c < 4; c++) {
        float dot11 = a1v[0]*s1[0][c] + a1v[1]*s1[1][c] + a1v[2]*s1[2][c];
        float dot22 = 0.f;
        #pragma unroll
        for (int q = 0; q < 9; q++) dot22 = fmaf(a2v[q], s2[q][c], dot22);
        o0[c] = w[0][c] * (a0v * s0[c]) + w[1][c] * dot11 + w[2][c] * dot22;
    }
    red4(ap, o0[0], o0[1], o0[2], o0[3]);

    #pragma unroll
    for (int i = 0; i < 3; i++) {
        float o1[4];
        #pragma unroll
        for (int c = 0; c < 4; c++) {
            float m21 = 0.f, m12 = 0.f;
            #pragma unroll
            for (int j = 0; j < 3; j++) {
                m21 = fmaf(a2v[i*3 + j], s1[j][c], m21);
                m12 = fmaf(a1v[j], s2[i*3 + j][c], m12);
            }
            o1[c] = w[3][c]*(a1v[i]*s0[c]) + w[4][c]*(a0v*s1[i][c]) + w[5][c]*m21 + w[6][c]*m12;
        }
        red4(ap + (1 + i) * CC, o1[0], o1[1], o1[2], o1[3]);
    }

    #pragma unroll
    for (int i = 0; i < 3; i++) {
        #pragma unroll
        for (int j = 0; j < 3; j++) {
            float o2[4];
            #pragma unroll
            for (int c = 0; c < 4; c++) {
                float mm = 0.f;
                #pragma unroll
                for (int kk = 0; kk < 3; kk++)
                    mm = fmaf(a2v[i*3 + kk], s2[kk*3 + j][c], mm);
                o2[c] = w[7][c]*(a1v[i]*s1[j][c]) + w[8][c]*(a2v[i*3+j]*s0[c])
                      + w[9][c]*(a0v*s2[i*3+j][c]) + w[10][c]*mm;
            }
            red4(ap + (4 + i*3 + j) * CC, o2[0], o2[1], o2[2], o2[3]);
        }
    }
}

// ---------------------------------------------------------------------------
__global__ void k_final(const float* __restrict__ D0, const float* __restrict__ D1,
                        const float* __restrict__ D2, float* __restrict__ out, int N)
{
    int idx = blockIdx.x * blockDim.x + threadIdx.x;
    if (idx >= N * CC) return;
    const int n = idx >> 6, c = idx & 63;
    const float inv = 1.0f / 32.0f;
    const float* __restrict__ ap = &g_acc[n * NCOMP * CC + c];

    float m0 = ap[0] * inv;
    float m1[3], m2[9];
    #pragma unroll
    for (int i = 0; i < 3; i++) m1[i] = ap[(1 + i) * CC] * inv;
    #pragma unroll
    for (int q = 0; q < 9; q++) m2[q] = ap[(4 + q) * CC] * inv;

    out[idx] = m0 * __ldg(&D0[0]);

    float* __restrict__ o1 = out + N * CC;
    #pragma unroll
    for (int j = 0; j < 3; j++) {
        float s = 0.f;
        #pragma unroll
        for (int i = 0; i < 3; i++) s = fmaf(m1[i], __ldg(&D1[i * 3 + j]), s);
        o1[idx * 3 + j] = s;
    }
    float* __restrict__ o2 = out + N * CC * 4;
    #pragma unroll
    for (int q = 0; q < 9; q++) {
        float s = 0.f;
        #pragma unroll
        for (int p = 0; p < 9; p++) s = fmaf(m2[p], __ldg(&D2[p * 9 + q]), s);
        o2[idx * 9 + q] = s;
    }
}

// ---------------------------------------------------------------------------
extern "C" void kernel_launch(void* const* d_in, const int* in_sizes, int n_in,
                              void* d_out, int out_size)
{
    const float* t0  = (const float*)d_in[0];
    const float* t1  = (const float*)d_in[1];
    const float* t2  = (const float*)d_in[2];
    const float* a0  = (const float*)d_in[3];
    const float* a1  = (const float*)d_in[4];
    const float* a2  = (const float*)d_in[5];
    const float* ef  = (const float*)d_in[6];
    const float* cut = (const float*)d_in[7];
    const float* W0  = (const float*)d_in[8];
    const float* W1  = (const float*)d_in[9];
    const float* W2  = (const float*)d_in[10];
    const float* Wr0 = (const float*)d_in[11];
    const float* Wr1 = (const float*)d_in[12];
    const float* Wr2 = (const float*)d_in[13];
    const float* Wr3 = (const float*)d_in[14];
    const float* D0  = (const float*)d_in[15];
    const float* D1  = (const float*)d_in[16];
    const float* D2  = (const float*)d_in[17];
    const int*   ei  = (const int*)d_in[18];

    const int N = in_sizes[0] / CC;   // 8000
    const int E = in_sizes[3];        // 256000
    float* out = (float*)d_out;

    cudaFuncSetAttribute(k_wgemm, cudaFuncAttributeMaxDynamicSharedMemorySize, SM_TOT);

    const int n4 = (N * NCOMP * CC) / 4;
    k_zero<<<(n4 + 255) / 256, 256>>>(n4);
    k_linear_up<<<N, 128>>>(t0, t1, t2, W0, W1, W2);
    k_mlp<<<(E + MLP_EPB - 1) / MLP_EPB, 512>>>(ef, Wr0, Wr1, Wr2, E);
    k_wgemm<<<(E + GEPB - 1) / GEPB, 256, SM_TOT>>>(Wr3, cut, E);
    k_tp<<<(E + TEPB - 1) / TEPB, 256>>>(a0, a1, a2, ei, E);
    k_final<<<(N * CC + 255) / 256, 256>>>(D0, D1, D2, out, N);
}

// round 5
// speedup vs baseline: 2.4711x; 1.1056x over previous
#include <cuda_runtime.h>
#include <cstdint>

#define CC     64
#define NCOMP  13
#define NPATHS 11
#define RR     8
#define HH     64
#define MAXN   8000
#define MAXE   256000
#define WCOLS  (NPATHS * CC)   // 704

__device__ __align__(16) float g_u[MAXN * NCOMP * CC];
__device__ __align__(16) float g_acc[MAXN * NCOMP * CC];
__device__ __align__(16) float g_h[MAXE * HH];
__device__ __align__(16) float g_w[(size_t)MAXE * WCOLS];
__device__ __align__(16) float g_wr3[HH * WCOLS];   // tf32-rounded Wr3

typedef unsigned long long u64t;

__device__ __forceinline__ u64t pack2(float lo, float hi) {
    u64t r; asm("mov.b64 %0,{%1,%2};" : "=l"(r) : "f"(lo), "f"(hi)); return r;
}
__device__ __forceinline__ void unpack2(u64t v, float& lo, float& hi) {
    asm("mov.b64 {%0,%1},%2;" : "=f"(lo), "=f"(hi) : "l"(v));
}
__device__ __forceinline__ u64t fma2(u64t a, u64t b, u64t c) {
    u64t d; asm("fma.rn.f32x2 %0,%1,%2,%3;" : "=l"(d) : "l"(a), "l"(b), "l"(c)); return d;
}
__device__ __forceinline__ void red4(float* p, float x, float y, float z, float w) {
    asm volatile("red.global.add.v4.f32 [%0], {%1,%2,%3,%4};"
                 :: "l"(p), "f"(x), "f"(y), "f"(z), "f"(w) : "memory");
}
__device__ __forceinline__ float silu(float x) { return x / (1.0f + __expf(-x)); }
__device__ __forceinline__ float cvt_tf32(float x) {
    uint32_t u; asm("cvt.rna.tf32.f32 %0, %1;" : "=r"(u) : "f"(x));
    return __uint_as_float(u);
}
__device__ __forceinline__ void mma_tf32(float& d0, float& d1, float& d2, float& d3,
                                         uint32_t a0, uint32_t a1, uint32_t a2, uint32_t a3,
                                         uint32_t b0, uint32_t b1) {
    asm volatile("mma.sync.aligned.m16n8k8.row.col.f32.tf32.tf32.f32 "
                 "{%0,%1,%2,%3}, {%4,%5,%6,%7}, {%8,%9}, {%0,%1,%2,%3};"
                 : "+f"(d0), "+f"(d1), "+f"(d2), "+f"(d3)
                 : "r"(a0), "r"(a1), "r"(a2), "r"(a3), "r"(b0), "r"(b1));
}

// ---------------------------------------------------------------------------
__global__ void k_zero(int n4) {
    int i = blockIdx.x * blockDim.x + threadIdx.x;
    if (i < n4) reinterpret_cast<float4*>(g_acc)[i] = make_float4(0.f, 0.f, 0.f, 0.f);
}

// round Wr3 -> tf32 once
__global__ void k_cvtw(const float* __restrict__ Wr3) {
    int i = blockIdx.x * blockDim.x + threadIdx.x;
    if (i < HH * WCOLS / 4) {
        float4 v = reinterpret_cast<const float4*>(Wr3)[i];
        v.x = cvt_tf32(v.x); v.y = cvt_tf32(v.y); v.z = cvt_tf32(v.z); v.w = cvt_tf32(v.w);
        reinterpret_cast<float4*>(g_wr3)[i] = v;
    }
}

// ---------------------------------------------------------------------------
__global__ void __launch_bounds__(128) k_linear_up(
    const float* __restrict__ t0, const float* __restrict__ t1, const float* __restrict__ t2,
    const float* __restrict__ W0, const float* __restrict__ W1, const float* __restrict__ W2)
{
    __shared__ float s_t[NCOMP][CC];
    const int n = blockIdx.x, tid = threadIdx.x;
    for (int idx = tid; idx < NCOMP * CC; idx += 128) {
        int comp = idx >> 6, c = idx & 63;
        float v;
        if (comp == 0)      v = t0[n * CC + c];
        else if (comp < 4)  v = t1[(n * CC + c) * 3 + (comp - 1)];
        else                v = t2[(n * CC + c) * 9 + (comp - 4)];
        s_t[comp][c] = v;
    }
    __syncthreads();
    for (int out = tid; out < NCOMP * CC; out += 128) {
        int comp = out >> 6, d = out & 63;
        const float* __restrict__ W = (comp == 0) ? W0 : ((comp < 4) ? W1 : W2);
        float acc = 0.f;
        #pragma unroll
        for (int c = 0; c < CC; c++) acc = fmaf(s_t[comp][c], __ldg(&W[c * CC + d]), acc);
        g_u[(n * NCOMP + comp) * CC + d] = acc;
    }
}

// ---------------------------------------------------------------------------
#define MLP_EPB 64
__global__ void __launch_bounds__(512) k_mlp(
    const float* __restrict__ ef, const float* __restrict__ Wr0,
    const float* __restrict__ Wr1, const float* __restrict__ Wr2, int E)
{
    __shared__ float s_f[MLP_EPB][RR];
    __shared__ float s_h1[HH][MLP_EPB + 2];
    __shared__ float s_h2[HH][MLP_EPB + 2];
    const int tid = threadIdx.x;
    const int e0  = blockIdx.x * MLP_EPB;
    {
        int e = tid >> 3, r = tid & 7;
        int ge = e0 + e; if (ge >= E) ge = E - 1;
        s_f[e][r] = ef[ge * RR + r];
    }
    __syncthreads();
    const int d = tid & 63, g = tid >> 6, eb = g * 8;

    #pragma unroll
    for (int el = 0; el < 8; el++) {
        float acc = 0.f;
        #pragma unroll
        for (int r = 0; r < RR; r++) acc = fmaf(s_f[eb + el][r], __ldg(&Wr0[r * HH + d]), acc);
        s_h1[d][eb + el] = silu(acc);
    }
    __syncthreads();
    {
        u64t a[4] = {0, 0, 0, 0};
        #pragma unroll 8
        for (int k = 0; k < HH; k++) {
            float wv = __ldg(&Wr1[k * HH + d]); u64t wv2 = pack2(wv, wv);
            const u64t* h = (const u64t*)&s_h1[k][eb];
            a[0] = fma2(h[0], wv2, a[0]); a[1] = fma2(h[1], wv2, a[1]);
            a[2] = fma2(h[2], wv2, a[2]); a[3] = fma2(h[3], wv2, a[3]);
        }
        #pragma unroll
        for (int m = 0; m < 4; m++) {
            float lo, hi; unpack2(a[m], lo, hi);
            s_h2[d][eb + 2*m] = silu(lo); s_h2[d][eb + 2*m + 1] = silu(hi);
        }
    }
    __syncthreads();
    {
        u64t a[4] = {0, 0, 0, 0};
        #pragma unroll 8
        for (int k = 0; k < HH; k++) {
            float wv = __ldg(&Wr2[k * HH + d]); u64t wv2 = pack2(wv, wv);
            const u64t* h = (const u64t*)&s_h2[k][eb];
            a[0] = fma2(h[0], wv2, a[0]); a[1] = fma2(h[1], wv2, a[1]);
            a[2] = fma2(h[2], wv2, a[2]); a[3] = fma2(h[3], wv2, a[3]);
        }
        #pragma unroll
        for (int m = 0; m < 4; m++) {
            float lo, hi; unpack2(a[m], lo, hi);
            s_h1[d][eb + 2*m]     = cvt_tf32(silu(lo));
            s_h1[d][eb + 2*m + 1] = cvt_tf32(silu(hi));
        }
    }
    __syncthreads();
    #pragma unroll
    for (int i = 0; i < 8; i++) {
        int flat = i * 512 + tid;
        int e = flat >> 6, dd = flat & 63;
        if (e0 + e < E) g_h[(size_t)(e0 + e) * HH + dd] = s_h1[dd][e];
    }
}

// ---------------------------------------------------------------------------
// tf32 mma.sync GEMM, B streamed from L1/L2 (no smem B):
// w[e][c] = (h3[e,:] @ Wr3[:,c]) * cutoff[e],  c in [0,704)
// Block: 256 thr / 128 edges. Warp grid: 4 along M (m32) x 2 along N (352).
// Per warp: A preloaded (64 regs), 22 n16-tiles, register-blocked m32n16.
#define GEPB   128
#define HPAD   68
__global__ void __launch_bounds__(256, 2) k_wgemm(const float* __restrict__ cut, int E)
{
    __shared__ float s_h[GEPB * HPAD];
    __shared__ float s_cut[GEPB];

    const int tid = threadIdx.x;
    const int e0  = blockIdx.x * GEPB;

    // stage h tile: 128 rows x 64 cols (tf32-rounded by k_mlp)
    #pragma unroll
    for (int i = 0; i < 8; i++) {
        int flat = i * 256 + tid;
        int row = flat >> 4, c4 = flat & 15;
        int ge = e0 + row; if (ge >= E) ge = E - 1;
        float4 v = *(const float4*)&g_h[(size_t)ge * HH + c4 * 4];
        *(float4*)&s_h[row * HPAD + c4 * 4] = v;
    }
    if (tid < GEPB) {
        int ge = e0 + tid; if (ge >= E) ge = E - 1;
        s_cut[tid] = cut[ge];
    }
    __syncthreads();

    const int wid  = tid >> 5, lane = tid & 31;
    const int gid  = lane >> 2, tig = lane & 3;
    const int mrow = wid & 3;        // 0..3 -> m32 slice
    const int ncol = wid >> 2;       // 0..1 -> 352-col half
    const int m0   = mrow * 32;
    const int nb0  = ncol * 352;

    const int ra0 = m0 + gid,      rb0 = m0 + gid + 8;
    const int ra1 = m0 + 16 + gid, rb1 = m0 + 16 + gid + 8;

    // preload A fragments: 8 ks x (slice0: 4 regs, slice1: 4 regs)
    uint32_t a[8][8];
    const uint32_t* hA = (const uint32_t*)s_h;
    #pragma unroll
    for (int ks = 0; ks < 8; ks++) {
        a[ks][0] = hA[ra0 * HPAD + ks * 8 + tig];
        a[ks][1] = hA[rb0 * HPAD + ks * 8 + tig];
        a[ks][2] = hA[ra0 * HPAD + ks * 8 + tig + 4];
        a[ks][3] = hA[rb0 * HPAD + ks * 8 + tig + 4];
        a[ks][4] = hA[ra1 * HPAD + ks * 8 + tig];
        a[ks][5] = hA[rb1 * HPAD + ks * 8 + tig];
        a[ks][6] = hA[ra1 * HPAD + ks * 8 + tig + 4];
        a[ks][7] = hA[rb1 * HPAD + ks * 8 + tig + 4];
    }
    const float ca0 = s_cut[ra0], cb0 = s_cut[rb0];
    const float ca1 = s_cut[ra1], cb1 = s_cut[rb1];
    const bool oka0 = (e0 + ra0) < E, okb0 = (e0 + rb0) < E;
    const bool oka1 = (e0 + ra1) < E, okb1 = (e0 + rb1) < E;

    const uint32_t* __restrict__ B = (const uint32_t*)g_wr3;

    #pragma unroll 1
    for (int j = 0; j < 22; j++) {
        const int nt0 = nb0 + j * 16;
        const int nt1 = nt0 + 8;
        float d[16];
        #pragma unroll
        for (int q = 0; q < 16; q++) d[q] = 0.f;

        #pragma unroll
        for (int ks = 0; ks < 8; ks++) {
            const int r0 = (ks * 8 + tig) * WCOLS;
            const int r1 = (ks * 8 + tig + 4) * WCOLS;
            uint32_t b0a = __ldg(&B[r0 + nt0 + gid]);
            uint32_t b1a = __ldg(&B[r1 + nt0 + gid]);
            uint32_t b0b = __ldg(&B[r0 + nt1 + gid]);
            uint32_t b1b = __ldg(&B[r1 + nt1 + gid]);
            mma_tf32(d[0], d[1], d[2], d[3],   a[ks][0], a[ks][1], a[ks][2], a[ks][3], b0a, b1a);
            mma_tf32(d[4], d[5], d[6], d[7],   a[ks][0], a[ks][1], a[ks][2], a[ks][3], b0b, b1b);
            mma_tf32(d[8], d[9], d[10], d[11], a[ks][4], a[ks][5], a[ks][6], a[ks][7], b0a, b1a);
            mma_tf32(d[12], d[13], d[14], d[15], a[ks][4], a[ks][5], a[ks][6], a[ks][7], b0b, b1b);
        }
        const int c0 = nt0 + tig * 2;
        const int c1 = nt1 + tig * 2;
        if (oka0) {
            *(float2*)&g_w[(size_t)(e0 + ra0) * WCOLS + c0] = make_float2(d[0] * ca0, d[1] * ca0);
            *(float2*)&g_w[(size_t)(e0 + ra0) * WCOLS + c1] = make_float2(d[4] * ca0, d[5] * ca0);
        }
        if (okb0) {
            *(float2*)&g_w[(size_t)(e0 + rb0) * WCOLS + c0] = make_float2(d[2] * cb0, d[3] * cb0);
            *(float2*)&g_w[(size_t)(e0 + rb0) * WCOLS + c1] = make_float2(d[6] * cb0, d[7] * cb0);
        }
        if (oka1) {
            *(float2*)&g_w[(size_t)(e0 + ra1) * WCOLS + c0] = make_float2(d[8] * ca1, d[9] * ca1);
            *(float2*)&g_w[(size_t)(e0 + ra1) * WCOLS + c1] = make_float2(d[12] * ca1, d[13] * ca1);
        }
        if (okb1) {
            *(float2*)&g_w[(size_t)(e0 + rb1) * WCOLS + c0] = make_float2(d[10] * cb1, d[11] * cb1);
            *(float2*)&g_w[(size_t)(e0 + rb1) * WCOLS + c1] = make_float2(d[14] * cb1, d[15] * cb1);
        }
    }
}

// ---------------------------------------------------------------------------
// TP + scatter: 16 edges/block, thread = (edge, channel-quad)
#define TEPB 16
__global__ void __launch_bounds__(256) k_tp(
    const float* __restrict__ a0g, const float* __restrict__ a1g, const float* __restrict__ a2g,
    const int* __restrict__ ei, int E)
{
    __shared__ float s_a[TEPB][16];
    const int tid = threadIdx.x;
    const int e0  = blockIdx.x * TEPB;

    if (tid < TEPB * 13) {
        int e = tid / 13, k = tid - 13 * e;
        int ge = e0 + e; if (ge >= E) ge = E - 1;
        float v;
        if (k == 0)     v = a0g[ge];
        else if (k < 4) v = a1g[ge * 3 + (k - 1)];
        else            v = a2g[ge * 9 + (k - 4)];
        s_a[e][k] = v;
    }
    __syncthreads();

    const int e  = tid >> 4;
    const int c0 = (tid & 15) * 4;
    const int ge = e0 + e;
    if (ge >= E) return;
    const int src = __ldg(&ei[ge]);
    const int dst = __ldg(&ei[E + ge]);

    const float* __restrict__ up = &g_u[src * NCOMP * CC + c0];
    float s0[4], s1[3][4], s2[9][4];
    *(float4*)s0 = __ldg((const float4*)&up[0]);
    #pragma unroll
    for (int i = 0; i < 3; i++) *(float4*)s1[i] = __ldg((const float4*)&up[(1 + i) * CC]);
    #pragma unroll
    for (int q = 0; q < 9; q++) *(float4*)s2[q] = __ldg((const float4*)&up[(4 + q) * CC]);

    float av[13];
    #pragma unroll
    for (int k = 0; k < 13; k++) av[k] = s_a[e][k];
    const float  a0v = av[0];
    const float* a1v = av + 1;
    const float* a2v = av + 4;

    float w[NPATHS][4];
    #pragma unroll
    for (int p = 0; p < NPATHS; p++)
        *(float4*)w[p] = __ldg((const float4*)&g_w[(size_t)ge * WCOLS + p * CC + c0]);

    float* __restrict__ ap = &g_acc[dst * NCOMP * CC + c0];

    float o0[4];
    #pragma unroll
    for (int c = 0; c < 4; c++) {
        float dot11 = a1v[0]*s1[0][c] + a1v[1]*s1[1][c] + a1v[2]*s1[2][c];
        float dot22 = 0.f;
        #pragma unroll
        for (int q = 0; q < 9; q++) dot22 = fmaf(a2v[q], s2[q][c], dot22);
        o0[c] = w[0][c] * (a0v * s0[c]) + w[1][c] * dot11 + w[2][c] * dot22;
    }
    red4(ap, o0[0], o0[1], o0[2], o0[3]);

    #pragma unroll
    for (int i = 0; i < 3; i++) {
        float o1[4];
        #pragma unroll
        for (int c = 0; c < 4; c++) {
            float m21 = 0.f, m12 = 0.f;
            #pragma unroll
            for (int j = 0; j < 3; j++) {
                m21 = fmaf(a2v[i*3 + j], s1[j][c], m21);
                m12 = fmaf(a1v[j], s2[i*3 + j][c], m12);
            }
            o1[c] = w[3][c]*(a1v[i]*s0[c]) + w[4][c]*(a0v*s1[i][c]) + w[5][c]*m21 + w[6][c]*m12;
        }
        red4(ap + (1 + i) * CC, o1[0], o1[1], o1[2], o1[3]);
    }

    #pragma unroll
    for (int i = 0; i < 3; i++) {
        #pragma unroll
        for (int j = 0; j < 3; j++) {
            float o2[4];
            #pragma unroll
            for (int c = 0; c < 4; c++) {
                float mm = 0.f;
                #pragma unroll
                for (int kk = 0; kk < 3; kk++)
                    mm = fmaf(a2v[i*3 + kk], s2[kk*3 + j][c], mm);
                o2[c] = w[7][c]*(a1v[i]*s1[j][c]) + w[8][c]*(a2v[i*3+j]*s0[c])
                      + w[9][c]*(a0v*s2[i*3+j][c]) + w[10][c]*mm;
            }
            red4(ap + (4 + i*3 + j) * CC, o2[0], o2[1], o2[2], o2[3]);
        }
    }
}

// ---------------------------------------------------------------------------
__global__ void k_final(const float* __restrict__ D0, const float* __restrict__ D1,
                        const float* __restrict__ D2, float* __restrict__ out, int N)
{
    int idx = blockIdx.x * blockDim.x + threadIdx.x;
    if (idx >= N * CC) return;
    const int n = idx >> 6, c = idx & 63;
    const float inv = 1.0f / 32.0f;
    const float* __restrict__ ap = &g_acc[n * NCOMP * CC + c];

    float m0 = ap[0] * inv;
    float m1[3], m2[9];
    #pragma unroll
    for (int i = 0; i < 3; i++) m1[i] = ap[(1 + i) * CC] * inv;
    #pragma unroll
    for (int q = 0; q < 9; q++) m2[q] = ap[(4 + q) * CC] * inv;

    out[idx] = m0 * __ldg(&D0[0]);

    float* __restrict__ o1 = out + N * CC;
    #pragma unroll
    for (int j = 0; j < 3; j++) {
        float s = 0.f;
        #pragma unroll
        for (int i = 0; i < 3; i++) s = fmaf(m1[i], __ldg(&D1[i * 3 + j]), s);
        o1[idx * 3 + j] = s;
    }
    float* __restrict__ o2 = out + N * CC * 4;
    #pragma unroll
    for (int q = 0; q < 9; q++) {
        float s = 0.f;
        #pragma unroll
        for (int p = 0; p < 9; p++) s = fmaf(m2[p], __ldg(&D2[p * 9 + q]), s);
        o2[idx * 9 + q] = s;
    }
}

// ---------------------------------------------------------------------------
extern "C" void kernel_launch(void* const* d_in, const int* in_sizes, int n_in,
                              void* d_out, int out_size)
{
    const float* t0  = (const float*)d_in[0];
    const float* t1  = (const float*)d_in[1];
    const float* t2  = (const float*)d_in[2];
    const float* a0  = (const float*)d_in[3];
    const float* a1  = (const float*)d_in[4];
    const float* a2  = (const float*)d_in[5];
    const float* ef  = (const float*)d_in[6];
    const float* cut = (const float*)d_in[7];
    const float* W0  = (const float*)d_in[8];
    const float* W1  = (const float*)d_in[9];
    const float* W2  = (const float*)d_in[10];
    const float* Wr0 = (const float*)d_in[11];
    const float* Wr1 = (const float*)d_in[12];
    const float* Wr2 = (const float*)d_in[13];
    const float* Wr3 = (const float*)d_in[14];
    const float* D0  = (const float*)d_in[15];
    const float* D1  = (const float*)d_in[16];
    const float* D2  = (const float*)d_in[17];
    const int*   ei  = (const int*)d_in[18];

    const int N = in_sizes[0] / CC;   // 8000
    const int E = in_sizes[3];        // 256000
    float* out = (float*)d_out;

    const int n4 = (N * NCOMP * CC) / 4;
    k_zero<<<(n4 + 255) / 256, 256>>>(n4);
    k_cvtw<<<(HH * WCOLS / 4 + 255) / 256, 256>>>(Wr3);
    k_linear_up<<<N, 128>>>(t0, t1, t2, W0, W1, W2);
    k_mlp<<<(E + MLP_EPB - 1) / MLP_EPB, 512>>>(ef, Wr0, Wr1, Wr2, E);
    k_wgemm<<<(E + GEPB - 1) / GEPB, 256>>>(cut, E);
    k_tp<<<(E + TEPB - 1) / TEPB, 256>>>(a0, a1, a2, ei, E);
    k_final<<<(N * CC + 255) / 256, 256>>>(D0, D1, D2, out, N);
}

// round 7
// speedup vs baseline: 2.5727x; 1.0411x over previous
#include <cuda_runtime.h>
#include <cstdint>

#define CC     64
#define NCOMP  13
#define NPATHS 11
#define RR     8
#define HH     64
#define MAXN   8000
#define MAXE   256000
#define WCOLS  (NPATHS * CC)   // 704

__device__ __align__(16) float g_u[MAXN * NCOMP * CC];
__device__ __align__(16) float g_acc[MAXN * NCOMP * CC];
__device__ __align__(16) float g_h[MAXE * HH];
__device__ __align__(16) float g_wr3[HH * WCOLS];   // tf32-rounded Wr3

typedef unsigned long long u64t;

__device__ __forceinline__ u64t pack2(float lo, float hi) {
    u64t r; asm("mov.b64 %0,{%1,%2};" : "=l"(r) : "f"(lo), "f"(hi)); return r;
}
__device__ __forceinline__ void unpack2(u64t v, float& lo, float& hi) {
    asm("mov.b64 {%0,%1},%2;" : "=f"(lo), "=f"(hi) : "l"(v));
}
__device__ __forceinline__ u64t fma2(u64t a, u64t b, u64t c) {
    u64t d; asm("fma.rn.f32x2 %0,%1,%2,%3;" : "=l"(d) : "l"(a), "l"(b), "l"(c)); return d;
}
__device__ __forceinline__ void red4(float* p, float x, float y, float z, float w) {
    asm volatile("red.global.add.v4.f32 [%0], {%1,%2,%3,%4};"
                 :: "l"(p), "f"(x), "f"(y), "f"(z), "f"(w) : "memory");
}
__device__ __forceinline__ float silu(float x) { return x / (1.0f + __expf(-x)); }
__device__ __forceinline__ float cvt_tf32(float x) {
    uint32_t u; asm("cvt.rna.tf32.f32 %0, %1;" : "=r"(u) : "f"(x));
    return __uint_as_float(u);
}
__device__ __forceinline__ void mma_tf32(float& d0, float& d1, float& d2, float& d3,
                                         uint32_t a0, uint32_t a1, uint32_t a2, uint32_t a3,
                                         uint32_t b0, uint32_t b1) {
    asm volatile("mma.sync.aligned.m16n8k8.row.col.f32.tf32.tf32.f32 "
                 "{%0,%1,%2,%3}, {%4,%5,%6,%7}, {%8,%9}, {%0,%1,%2,%3};"
                 : "+f"(d0), "+f"(d1), "+f"(d2), "+f"(d3)
                 : "r"(a0), "r"(a1), "r"(a2), "r"(a3), "r"(b0), "r"(b1));
}

// ---------------------------------------------------------------------------
__global__ void k_zero(int n4) {
    int i = blockIdx.x * blockDim.x + threadIdx.x;
    if (i < n4) reinterpret_cast<float4*>(g_acc)[i] = make_float4(0.f, 0.f, 0.f, 0.f);
}

__global__ void k_cvtw(const float* __restrict__ Wr3) {
    int i = blockIdx.x * blockDim.x + threadIdx.x;
    if (i < HH * WCOLS / 4) {
        float4 v = reinterpret_cast<const float4*>(Wr3)[i];
        v.x = cvt_tf32(v.x); v.y = cvt_tf32(v.y); v.z = cvt_tf32(v.z); v.w = cvt_tf32(v.w);
        reinterpret_cast<float4*>(g_wr3)[i] = v;
    }
}

// ---------------------------------------------------------------------------
__global__ void __launch_bounds__(128) k_linear_up(
    const float* __restrict__ t0, const float* __restrict__ t1, const float* __restrict__ t2,
    const float* __restrict__ W0, const float* __restrict__ W1, const float* __restrict__ W2)
{
    __shared__ float s_t[NCOMP][CC];
    const int n = blockIdx.x, tid = threadIdx.x;
    for (int idx = tid; idx < NCOMP * CC; idx += 128) {
        int comp = idx >> 6, c = idx & 63;
        float v;
        if (comp == 0)      v = t0[n * CC + c];
        else if (comp < 4)  v = t1[(n * CC + c) * 3 + (comp - 1)];
        else                v = t2[(n * CC + c) * 9 + (comp - 4)];
        s_t[comp][c] = v;
    }
    __syncthreads();
    for (int out = tid; out < NCOMP * CC; out += 128) {
        int comp = out >> 6, d = out & 63;
        const float* __restrict__ W = (comp == 0) ? W0 : ((comp < 4) ? W1 : W2);
        float acc = 0.f;
        #pragma unroll
        for (int c = 0; c < CC; c++) acc = fmaf(s_t[comp][c], __ldg(&W[c * CC + d]), acc);
        g_u[(n * NCOMP + comp) * CC + d] = acc;
    }
}

// ---------------------------------------------------------------------------
#define MLP_EPB 64
__global__ void __launch_bounds__(512) k_mlp(
    const float* __restrict__ ef, const float* __restrict__ Wr0,
    const float* __restrict__ Wr1, const float* __restrict__ Wr2, int E)
{
    __shared__ float s_f[MLP_EPB][RR];
    __shared__ float s_h1[HH][MLP_EPB + 2];
    __shared__ float s_h2[HH][MLP_EPB + 2];
    const int tid = threadIdx.x;
    const int e0  = blockIdx.x * MLP_EPB;
    {
        int e = tid >> 3, r = tid & 7;
        int ge = e0 + e; if (ge >= E) ge = E - 1;
        s_f[e][r] = ef[ge * RR + r];
    }
    __syncthreads();
    const int d = tid & 63, g = tid >> 6, eb = g * 8;

    #pragma unroll
    for (int el = 0; el < 8; el++) {
        float acc = 0.f;
        #pragma unroll
        for (int r = 0; r < RR; r++) acc = fmaf(s_f[eb + el][r], __ldg(&Wr0[r * HH + d]), acc);
        s_h1[d][eb + el] = silu(acc);
    }
    __syncthreads();
    {
        u64t a[4] = {0, 0, 0, 0};
        #pragma unroll 8
        for (int k = 0; k < HH; k++) {
            float wv = __ldg(&Wr1[k * HH + d]); u64t wv2 = pack2(wv, wv);
            const u64t* h = (const u64t*)&s_h1[k][eb];
            a[0] = fma2(h[0], wv2, a[0]); a[1] = fma2(h[1], wv2, a[1]);
            a[2] = fma2(h[2], wv2, a[2]); a[3] = fma2(h[3], wv2, a[3]);
        }
        #pragma unroll
        for (int m = 0; m < 4; m++) {
            float lo, hi; unpack2(a[m], lo, hi);
            s_h2[d][eb + 2*m] = silu(lo); s_h2[d][eb + 2*m + 1] = silu(hi);
        }
    }
    __syncthreads();
    {
        u64t a[4] = {0, 0, 0, 0};
        #pragma unroll 8
        for (int k = 0; k < HH; k++) {
            float wv = __ldg(&Wr2[k * HH + d]); u64t wv2 = pack2(wv, wv);
            const u64t* h = (const u64t*)&s_h2[k][eb];
            a[0] = fma2(h[0], wv2, a[0]); a[1] = fma2(h[1], wv2, a[1]);
            a[2] = fma2(h[2], wv2, a[2]); a[3] = fma2(h[3], wv2, a[3]);
        }
        #pragma unroll
        for (int m = 0; m < 4; m++) {
            float lo, hi; unpack2(a[m], lo, hi);
            s_h1[d][eb + 2*m]     = cvt_tf32(silu(lo));
            s_h1[d][eb + 2*m + 1] = cvt_tf32(silu(hi));
        }
    }
    __syncthreads();
    #pragma unroll
    for (int i = 0; i < 8; i++) {
        int flat = i * 512 + tid;
        int e = flat >> 6, dd = flat & 63;
        if (e0 + e < E) g_h[(size_t)(e0 + e) * HH + dd] = s_h1[dd][e];
    }
}

// ---------------------------------------------------------------------------
// Fused GEMM (tf32 mma.sync) + tensor product + scatter. 16 edges / block.
// Dynamic smem layout (floats):
//   s_h   [16*68]          @ 0
//   s_w   [16*712]         @ 1088
//   s_a   [16*16]          @ 12480
//   s_cut [16]             @ 12736
//   s_src [16] (int)       @ 12752
//   s_dst [16] (int)       @ 12768
//   total 12784 floats = 51136 B
#define FEPB 16
#define FHP  68
#define PS   712
#define FO_H    0
#define FO_W    1088
#define FO_A    12480
#define FO_CUT  12736
#define FO_SRC  12752
#define FO_DST  12768
#define F_SMEM  (12784 * 4)

__global__ void __launch_bounds__(256) k_fused(
    const float* __restrict__ a0g, const float* __restrict__ a1g, const float* __restrict__ a2g,
    const float* __restrict__ cut, const int* __restrict__ ei, int E)
{
    extern __shared__ float sm[];
    float* s_h   = sm + FO_H;
    float* s_w   = sm + FO_W;
    float* s_a   = sm + FO_A;
    float* s_cut = sm + FO_CUT;
    int*   s_src = (int*)(sm + FO_SRC);
    int*   s_dst = (int*)(sm + FO_DST);

    const int tid = threadIdx.x;
    const int e0  = blockIdx.x * FEPB;

    // stage h tile (16x64) + per-edge small data
    {
        int row = tid >> 4, c4 = tid & 15;
        int ge = e0 + row; if (ge >= E) ge = E - 1;
        *(float4*)&s_h[row * FHP + c4 * 4] = *(const float4*)&g_h[(size_t)ge * HH + c4 * 4];
    }
    if (tid < FEPB * 13) {
        int e = tid / 13, k = tid - 13 * e;
        int ge = e0 + e; if (ge >= E) ge = E - 1;
        float v;
        if (k == 0)     v = a0g[ge];
        else if (k < 4) v = a1g[ge * 3 + (k - 1)];
        else            v = a2g[ge * 9 + (k - 4)];
        s_a[e * 16 + k] = v;
    }
    if (tid < FEPB) {
        int ge = e0 + tid; if (ge >= E) ge = E - 1;
        s_cut[tid] = cut[ge];
        s_src[tid] = ei[ge];
        s_dst[tid] = ei[E + ge];
    }
    __syncthreads();

    // ---- phase 1: GEMM ----
    {
        const int wid = tid >> 5, lane = tid & 31;
        const int gid = lane >> 2, tig = lane & 3;

        uint32_t a[8][4];
        const uint32_t* hA = (const uint32_t*)s_h;
        #pragma unroll
        for (int ks = 0; ks < 8; ks++) {
            a[ks][0] = hA[gid * FHP + ks * 8 + tig];
            a[ks][1] = hA[(gid + 8) * FHP + ks * 8 + tig];
            a[ks][2] = hA[gid * FHP + ks * 8 + tig + 4];
            a[ks][3] = hA[(gid + 8) * FHP + ks * 8 + tig + 4];
        }
        const float cA = s_cut[gid], cB = s_cut[gid + 8];
        const uint32_t* __restrict__ B = (const uint32_t*)g_wr3;
        const int ncol = wid * 8 + gid;

        #pragma unroll
        for (int p = 0; p < NPATHS; p++) {
            float d0 = 0.f, d1 = 0.f, d2 = 0.f, d3 = 0.f;
            const int nb = p * CC + ncol;
            #pragma unroll
            for (int ks = 0; ks < 8; ks++) {
                uint32_t b0 = __ldg(&B[(ks * 8 + tig) * WCOLS + nb]);
                uint32_t b1 = __ldg(&B[(ks * 8 + tig + 4) * WCOLS + nb]);
                mma_tf32(d0, d1, d2, d3, a[ks][0], a[ks][1], a[ks][2], a[ks][3], b0, b1);
            }
            const int c = p * 64 + wid * 8 + tig * 2;
            *(float2*)&s_w[gid * PS + c]       = make_float2(d0 * cA, d1 * cA);
            *(float2*)&s_w[(gid + 8) * PS + c] = make_float2(d2 * cB, d3 * cB);
        }
    }
    __syncthreads();

    // ---- phase 2: tensor product + scatter ----
    {
        const int e  = tid >> 4;
        const int c0 = (tid & 15) * 4;
        const int ge = e0 + e;
        if (ge >= E) return;
        const int src = s_src[e];
        const int dst = s_dst[e];

        const float* __restrict__ up = &g_u[src * NCOMP * CC + c0];
        float s0[4], s1[3][4], s2[9][4];
        *(float4*)s0 = __ldg((const float4*)&up[0]);
        #pragma unroll
        for (int i = 0; i < 3; i++) *(float4*)s1[i] = __ldg((const float4*)&up[(1 + i) * CC]);
        #pragma unroll
        for (int q = 0; q < 9; q++) *(float4*)s2[q] = __ldg((const float4*)&up[(4 + q) * CC]);

        float av[13];
        #pragma unroll
        for (int k = 0; k < 13; k++) av[k] = s_a[e * 16 + k];
        const float  a0v = av[0];
        const float* a1v = av + 1;
        const float* a2v = av + 4;

        float w[NPATHS][4];
        #pragma unroll
        for (int p = 0; p < NPATHS; p++)
            *(float4*)w[p] = *(const float4*)&s_w[e * PS + p * CC + c0];

        float* __restrict__ ap = &g_acc[dst * NCOMP * CC + c0];

        float o0[4];
        #pragma unroll
        for (int c = 0; c < 4; c++) {
            float dot11 = a1v[0]*s1[0][c] + a1v[1]*s1[1][c] + a1v[2]*s1[2][c];
            float dot22 = 0.f;
            #pragma unroll
            for (int q = 0; q < 9; q++) dot22 = fmaf(a2v[q], s2[q][c], dot22);
            o0[c] = w[0][c] * (a0v * s0[c]) + w[1][c] * dot11 + w[2][c] * dot22;
        }
        red4(ap, o0[0], o0[1], o0[2], o0[3]);

        #pragma unroll
        for (int i = 0; i < 3; i++) {
            float o1[4];
            #pragma unroll
            for (int c = 0; c < 4; c++) {
                float m21 = 0.f, m12 = 0.f;
                #pragma unroll
                for (int j = 0; j < 3; j++) {
                    m21 = fmaf(a2v[i*3 + j], s1[j][c], m21);
                    m12 = fmaf(a1v[j], s2[i*3 + j][c], m12);
                }
                o1[c] = w[3][c]*(a1v[i]*s0[c]) + w[4][c]*(a0v*s1[i][c]) + w[5][c]*m21 + w[6][c]*m12;
            }
            red4(ap + (1 + i) * CC, o1[0], o1[1], o1[2], o1[3]);
        }

        #pragma unroll
        for (int i = 0; i < 3; i++) {
            #pragma unroll
            for (int j = 0; j < 3; j++) {
                float o2[4];
                #pragma unroll
                for (int c = 0; c < 4; c++) {
                    float mm = 0.f;
                    #pragma unroll
                    for (int kk = 0; kk < 3; kk++)
                        mm = fmaf(a2v[i*3 + kk], s2[kk*3 + j][c], mm);
                    o2[c] = w[7][c]*(a1v[i]*s1[j][c]) + w[8][c]*(a2v[i*3+j]*s0[c])
                          + w[9][c]*(a0v*s2[i*3+j][c]) + w[10][c]*mm;
                }
                red4(ap + (4 + i*3 + j) * CC, o2[0], o2[1], o2[2], o2[3]);
            }
        }
    }
}

// ---------------------------------------------------------------------------
__global__ void k_final(const float* __restrict__ D0, const float* __restrict__ D1,
                        const float* __restrict__ D2, float* __restrict__ out, int N)
{
    int idx = blockIdx.x * blockDim.x + threadIdx.x;
    if (idx >= N * CC) return;
    const int n = idx >> 6, c = idx & 63;
    const float inv = 1.0f / 32.0f;
    const float* __restrict__ ap = &g_acc[n * NCOMP * CC + c];

    float m0 = ap[0] * inv;
    float m1[3], m2[9];
    #pragma unroll
    for (int i = 0; i < 3; i++) m1[i] = ap[(1 + i) * CC] * inv;
    #pragma unroll
    for (int q = 0; q < 9; q++) m2[q] = ap[(4 + q) * CC] * inv;

    out[idx] = m0 * __ldg(&D0[0]);

    float* __restrict__ o1 = out + N * CC;
    #pragma unroll
    for (int j = 0; j < 3; j++) {
        float s = 0.f;
        #pragma unroll
        for (int i = 0; i < 3; i++) s = fmaf(m1[i], __ldg(&D1[i * 3 + j]), s);
        o1[idx * 3 + j] = s;
    }
    float* __restrict__ o2 = out + N * CC * 4;
    #pragma unroll
    for (int q = 0; q < 9; q++) {
        float s = 0.f;
        #pragma unroll
        for (int p = 0; p < 9; p++) s = fmaf(m2[p], __ldg(&D2[p * 9 + q]), s);
        o2[idx * 9 + q] = s;
    }
}

// ---------------------------------------------------------------------------
extern "C" void kernel_launch(void* const* d_in, const int* in_sizes, int n_in,
                              void* d_out, int out_size)
{
    const float* t0  = (const float*)d_in[0];
    const float* t1  = (const float*)d_in[1];
    const float* t2  = (const float*)d_in[2];
    const float* a0  = (const float*)d_in[3];
    const float* a1  = (const float*)d_in[4];
    const float* a2  = (const float*)d_in[5];
    const float* ef  = (const float*)d_in[6];
    const float* cut = (const float*)d_in[7];
    const float* W0  = (const float*)d_in[8];
    const float* W1  = (const float*)d_in[9];
    const float* W2  = (const float*)d_in[10];
    const float* Wr0 = (const float*)d_in[11];
    const float* Wr1 = (const float*)d_in[12];
    const float* Wr2 = (const float*)d_in[13];
    const float* Wr3 = (const float*)d_in[14];
    const float* D0  = (const float*)d_in[15];
    const float* D1  = (const float*)d_in[16];
    const float* D2  = (const float*)d_in[17];
    const int*   ei  = (const int*)d_in[18];

    const int N = in_sizes[0] / CC;   // 8000
    const int E = in_sizes[3];        // 256000
    float* out = (float*)d_out;

    cudaFuncSetAttribute(k_fused, cudaFuncAttributeMaxDynamicSharedMemorySize, F_SMEM);

    const int n4 = (N * NCOMP * CC) / 4;
    k_zero<<<(n4 + 255) / 256, 256>>>(n4);
    k_cvtw<<<(HH * WCOLS / 4 + 255) / 256, 256>>>(Wr3);
    k_linear_up<<<N, 128>>>(t0, t1, t2, W0, W1, W2);
    k_mlp<<<(E + MLP_EPB - 1) / MLP_EPB, 512>>>(ef, Wr0, Wr1, Wr2, E);
    k_fused<<<(E + FEPB - 1) / FEPB, 256, F_SMEM>>>(a0, a1, a2, cut, ei, E);
    k_final<<<(N * CC + 255) / 256, 256>>>(D0, D1, D2, out, N);
}

// round 9
// speedup vs baseline: 3.0888x; 1.2006x over previous
#include <cuda_runtime.h>
#include <cstdint>

#define CC     64
#define NCOMP  13
#define NPATHS 11
#define RR     8
#define HH     64
#define MAXN   8000
#define MAXE   256000
#define WCOLS  (NPATHS * CC)   // 704

__device__ __align__(16) float g_u[MAXN * NCOMP * CC];
__device__ __align__(16) float g_acc[MAXN * NCOMP * CC];
__device__ __align__(16) float g_h[MAXE * HH];
__device__ __align__(16) float g_wr0[RR * HH];      // tf32 weights
__device__ __align__(16) float g_wr1[HH * HH];
__device__ __align__(16) float g_wr2[HH * HH];
__device__ __align__(16) float g_wr3[HH * WCOLS];

__device__ __forceinline__ void red4(float* p, float x, float y, float z, float w) {
    asm volatile("red.global.add.v4.f32 [%0], {%1,%2,%3,%4};"
                 :: "l"(p), "f"(x), "f"(y), "f"(z), "f"(w) : "memory");
}
__device__ __forceinline__ float silu(float x) { return x / (1.0f + __expf(-x)); }
__device__ __forceinline__ float cvt_tf32(float x) {
    uint32_t u; asm("cvt.rna.tf32.f32 %0, %1;" : "=r"(u) : "f"(x));
    return __uint_as_float(u);
}
__device__ __forceinline__ void mma_tf32(float& d0, float& d1, float& d2, float& d3,
                                         uint32_t a0, uint32_t a1, uint32_t a2, uint32_t a3,
                                         uint32_t b0, uint32_t b1) {
    asm volatile("mma.sync.aligned.m16n8k8.row.col.f32.tf32.tf32.f32 "
                 "{%0,%1,%2,%3}, {%4,%5,%6,%7}, {%8,%9}, {%0,%1,%2,%3};"
                 : "+f"(d0), "+f"(d1), "+f"(d2), "+f"(d3)
                 : "r"(a0), "r"(a1), "r"(a2), "r"(a3), "r"(b0), "r"(b1));
}

// ---------------------------------------------------------------------------
__global__ void k_zero(int n4) {
    int i = blockIdx.x * blockDim.x + threadIdx.x;
    if (i < n4) reinterpret_cast<float4*>(g_acc)[i] = make_float4(0.f, 0.f, 0.f, 0.f);
}

// round all radial weights -> tf32 (float4 granularity)
__global__ void k_cvtw(const float* __restrict__ Wr0, const float* __restrict__ Wr1,
                       const float* __restrict__ Wr2, const float* __restrict__ Wr3) {
    int i = blockIdx.x * blockDim.x + threadIdx.x;
    const float4* src; float4* dst; int base;
    if (i < 128)             { src = (const float4*)Wr0; dst = (float4*)g_wr0; base = i; }
    else if (i < 1152)       { src = (const float4*)Wr1; dst = (float4*)g_wr1; base = i - 128; }
    else if (i < 2176)       { src = (const float4*)Wr2; dst = (float4*)g_wr2; base = i - 1152; }
    else if (i < 13440)      { src = (const float4*)Wr3; dst = (float4*)g_wr3; base = i - 2176; }
    else return;
    float4 v = src[base];
    v.x = cvt_tf32(v.x); v.y = cvt_tf32(v.y); v.z = cvt_tf32(v.z); v.w = cvt_tf32(v.w);
    dst[base] = v;
}

// ---------------------------------------------------------------------------
__global__ void __launch_bounds__(128) k_linear_up(
    const float* __restrict__ t0, const float* __restrict__ t1, const float* __restrict__ t2,
    const float* __restrict__ W0, const float* __restrict__ W1, const float* __restrict__ W2)
{
    __shared__ float s_t[NCOMP][CC];
    const int n = blockIdx.x, tid = threadIdx.x;
    for (int idx = tid; idx < NCOMP * CC; idx += 128) {
        int comp = idx >> 6, c = idx & 63;
        float v;
        if (comp == 0)      v = t0[n * CC + c];
        else if (comp < 4)  v = t1[(n * CC + c) * 3 + (comp - 1)];
        else                v = t2[(n * CC + c) * 9 + (comp - 4)];
        s_t[comp][c] = v;
    }
    __syncthreads();
    for (int out = tid; out < NCOMP * CC; out += 128) {
        int comp = out >> 6, d = out & 63;
        const float* __restrict__ W = (comp == 0) ? W0 : ((comp < 4) ? W1 : W2);
        float acc = 0.f;
        #pragma unroll
        for (int c = 0; c < CC; c++) acc = fmaf(s_t[comp][c], __ldg(&W[c * CC + d]), acc);
        g_u[(n * NCOMP + comp) * CC + d] = acc;
    }
}

// ---------------------------------------------------------------------------
// Tensor-core radial MLP. 128 edges / block, 256 threads (8 warps).
// Warp w owns edge rows [w*16, w*16+16) through ALL layers -> __syncwarp only.
#define MEPB 128
#define MHP  68
#define M_SMEM (18432 * 4)

__global__ void __launch_bounds__(256) k_mlp(const float* __restrict__ ef, int E)
{
    extern __shared__ float sm[];
    float* s_f  = sm;
    float* s_h1 = sm + 1024;
    float* s_h2 = sm + 9728;

    const int tid  = threadIdx.x;
    const int e0   = blockIdx.x * MEPB;
    const int lane = tid & 31;
    const int wid  = tid >> 5;
    const int gid  = lane >> 2, tig = lane & 3;
    const int m0   = wid * 16;
    const int ra   = m0 + gid, rb = ra + 8;

    // stage f (tf32-rounded): thread stages row tid>>1, half (tid&1)
    {
        int row = tid >> 1, q = (tid & 1) * 4;
        int ge = e0 + row; if (ge >= E) ge = E - 1;
        float4 v = *(const float4*)&ef[ge * RR + q];
        v.x = cvt_tf32(v.x); v.y = cvt_tf32(v.y); v.z = cvt_tf32(v.z); v.w = cvt_tf32(v.w);
        *(float4*)&s_f[row * RR + q] = v;
    }
    __syncwarp();

    const uint32_t* fA = (const uint32_t*)s_f;
    const uint32_t* h1A = (const uint32_t*)s_h1;
    const uint32_t* h2A = (const uint32_t*)s_h2;

    // ---- layer 1: h1 = silu(f @ Wr0), K=8 (one k-step) ----
    {
        uint32_t a0 = fA[ra * RR + tig], a1 = fA[rb * RR + tig];
        uint32_t a2 = fA[ra * RR + tig + 4], a3 = fA[rb * RR + tig + 4];
        const uint32_t* __restrict__ B = (const uint32_t*)g_wr0;
        #pragma unroll
        for (int nt = 0; nt < 8; nt++) {
            const int nb = nt * 8 + gid;
            float d0 = 0.f, d1 = 0.f, d2 = 0.f, d3 = 0.f;
            mma_tf32(d0, d1, d2, d3, a0, a1, a2, a3,
                     __ldg(&B[tig * HH + nb]), __ldg(&B[(tig + 4) * HH + nb]));
            const int c = nt * 8 + tig * 2;
            s_h1[ra * MHP + c]     = cvt_tf32(silu(d0));
            s_h1[ra * MHP + c + 1] = cvt_tf32(silu(d1));
            s_h1[rb * MHP + c]     = cvt_tf32(silu(d2));
            s_h1[rb * MHP + c + 1] = cvt_tf32(silu(d3));
        }
    }
    __syncwarp();

    // ---- layer 2: h2 = silu(h1 @ Wr1) ----
    {
        uint32_t a[8][4];
        #pragma unroll
        for (int ks = 0; ks < 8; ks++) {
            a[ks][0] = h1A[ra * MHP + ks * 8 + tig];
            a[ks][1] = h1A[rb * MHP + ks * 8 + tig];
            a[ks][2] = h1A[ra * MHP + ks * 8 + tig + 4];
            a[ks][3] = h1A[rb * MHP + ks * 8 + tig + 4];
        }
        const uint32_t* __restrict__ B = (const uint32_t*)g_wr1;
        #pragma unroll
        for (int nt = 0; nt < 8; nt++) {
            const int nb = nt * 8 + gid;
            float d0 = 0.f, d1 = 0.f, d2 = 0.f, d3 = 0.f;
            #pragma unroll
            for (int ks = 0; ks < 8; ks++)
                mma_tf32(d0, d1, d2, d3, a[ks][0], a[ks][1], a[ks][2], a[ks][3],
                         __ldg(&B[(ks * 8 + tig) * HH + nb]),
                         __ldg(&B[(ks * 8 + tig + 4) * HH + nb]));
            const int c = nt * 8 + tig * 2;
            s_h2[ra * MHP + c]     = cvt_tf32(silu(d0));
            s_h2[ra * MHP + c + 1] = cvt_tf32(silu(d1));
            s_h2[rb * MHP + c]     = cvt_tf32(silu(d2));
            s_h2[rb * MHP + c + 1] = cvt_tf32(silu(d3));
        }
    }
    __syncwarp();

    // ---- layer 3: h3 = silu(h2 @ Wr2) -> g_h (tf32) ----
    {
        uint32_t a[8][4];
        #pragma unroll
        for (int ks = 0; ks < 8; ks++) {
            a[ks][0] = h2A[ra * MHP + ks * 8 + tig];
            a[ks][1] = h2A[rb * MHP + ks * 8 + tig];
            a[ks][2] = h2A[ra * MHP + ks * 8 + tig + 4];
            a[ks][3] = h2A[rb * MHP + ks * 8 + tig + 4];
        }
        const uint32_t* __restrict__ B = (const uint32_t*)g_wr2;
        const int geA = e0 + ra, geB = e0 + rb;
        #pragma unroll
        for (int nt = 0; nt < 8; nt++) {
            const int nb = nt * 8 + gid;
            float d0 = 0.f, d1 = 0.f, d2 = 0.f, d3 = 0.f;
            #pragma unroll
            for (int ks = 0; ks < 8; ks++)
                mma_tf32(d0, d1, d2, d3, a[ks][0], a[ks][1], a[ks][2], a[ks][3],
                         __ldg(&B[(ks * 8 + tig) * HH + nb]),
                         __ldg(&B[(ks * 8 + tig + 4) * HH + nb]));
            const int c = nt * 8 + tig * 2;
            if (geA < E)
                *(float2*)&g_h[(size_t)geA * HH + c] =
                    make_float2(cvt_tf32(silu(d0)), cvt_tf32(silu(d1)));
            if (geB < E)
                *(float2*)&g_h[(size_t)geB * HH + c] =
                    make_float2(cvt_tf32(silu(d2)), cvt_tf32(silu(d3)));
        }
    }
}

// ---------------------------------------------------------------------------
// Fused GEMM + tensor product + scatter. 32 edges / block, 256 threads.
#define FEPB 32
#define FHP  68
#define PS   712
#define FO_W    2176
#define FO_A    24960
#define FO_CUT  25472
#define FO_SRC  25504
#define FO_DST  25536
#define F_SMEM  (25568 * 4)

__global__ void __launch_bounds__(256) k_fused(
    const float* __restrict__ a0g, const float* __restrict__ a1g, const float* __restrict__ a2g,
    const float* __restrict__ cut, const int* __restrict__ ei, int E)
{
    extern __shared__ float sm[];
    float* s_h   = sm;
    float* s_w   = sm + FO_W;
    float* s_a   = sm + FO_A;
    float* s_cut = sm + FO_CUT;
    int*   s_src = (int*)(sm + FO_SRC);
    int*   s_dst = (int*)(sm + FO_DST);

    const int tid = threadIdx.x;
    const int e0  = blockIdx.x * FEPB;

    // stage h tile (32x64) + per-edge small data
    #pragma unroll
    for (int i = 0; i < 2; i++) {
        int flat = i * 256 + tid;
        int row = flat >> 4, c4 = flat & 15;
        int ge = e0 + row; if (ge >= E) ge = E - 1;
        *(float4*)&s_h[row * FHP + c4 * 4] = *(const float4*)&g_h[(size_t)ge * HH + c4 * 4];
    }
    for (int idx = tid; idx < FEPB * 13; idx += 256) {   // FIX: strided (416 > 256)
        int e = idx / 13, k = idx - 13 * e;
        int ge = e0 + e; if (ge >= E) ge = E - 1;
        float v;
        if (k == 0)     v = a0g[ge];
        else if (k < 4) v = a1g[ge * 3 + (k - 1)];
        else            v = a2g[ge * 9 + (k - 4)];
        s_a[e * 16 + k] = v;
    }
    if (tid < FEPB) {
        int ge = e0 + tid; if (ge >= E) ge = E - 1;
        s_cut[tid] = cut[ge];
        s_src[tid] = ei[ge];
        s_dst[tid] = ei[E + ge];
    }
    __syncthreads();

    // ---- phase 1: GEMM, two m16 slices per warp share B fragments ----
    {
        const int wid = tid >> 5, lane = tid & 31;
        const int gid = lane >> 2, tig = lane & 3;

        uint32_t a[2][8][4];
        const uint32_t* hA = (const uint32_t*)s_h;
        #pragma unroll
        for (int s = 0; s < 2; s++) {
            const int rA = s * 16 + gid, rB = rA + 8;
            #pragma unroll
            for (int ks = 0; ks < 8; ks++) {
                a[s][ks][0] = hA[rA * FHP + ks * 8 + tig];
                a[s][ks][1] = hA[rB * FHP + ks * 8 + tig];
                a[s][ks][2] = hA[rA * FHP + ks * 8 + tig + 4];
                a[s][ks][3] = hA[rB * FHP + ks * 8 + tig + 4];
            }
        }
        const float cA0 = s_cut[gid],      cB0 = s_cut[gid + 8];
        const float cA1 = s_cut[gid + 16], cB1 = s_cut[gid + 24];
        const uint32_t* __restrict__ B = (const uint32_t*)g_wr3;
        const int ncol = wid * 8 + gid;

        #pragma unroll
        for (int p = 0; p < NPATHS; p++) {
            float d0[4] = {0.f, 0.f, 0.f, 0.f};
            float d1[4] = {0.f, 0.f, 0.f, 0.f};
            const int nb = p * CC + ncol;
            #pragma unroll
            for (int ks = 0; ks < 8; ks++) {
                uint32_t b0 = __ldg(&B[(ks * 8 + tig) * WCOLS + nb]);
                uint32_t b1 = __ldg(&B[(ks * 8 + tig + 4) * WCOLS + nb]);
                mma_tf32(d0[0], d0[1], d0[2], d0[3],
                         a[0][ks][0], a[0][ks][1], a[0][ks][2], a[0][ks][3], b0, b1);
                mma_tf32(d1[0], d1[1], d1[2], d1[3],
                         a[1][ks][0], a[1][ks][1], a[1][ks][2], a[1][ks][3], b0, b1);
            }
            const int c = p * 64 + wid * 8 + tig * 2;
            *(float2*)&s_w[gid * PS + c]        = make_float2(d0[0] * cA0, d0[1] * cA0);
            *(float2*)&s_w[(gid + 8) * PS + c]  = make_float2(d0[2] * cB0, d0[3] * cB0);
            *(float2*)&s_w[(gid + 16) * PS + c] = make_float2(d1[0] * cA1, d1[1] * cA1);
            *(float2*)&s_w[(gid + 24) * PS + c] = make_float2(d1[2] * cB1, d1[3] * cB1);
        }
    }
    __syncthreads();

    // ---- phase 2: tensor product + scatter, 2 edges per thread ----
    #pragma unroll
    for (int el = 0; el < 2; el++) {
        const int e  = (tid >> 4) + el * 16;
        const int c0 = (tid & 15) * 4;
        const int ge = e0 + e;
        if (ge >= E) continue;
        const int src = s_src[e];
        const int dst = s_dst[e];

        const float* __restrict__ up = &g_u[src * NCOMP * CC + c0];
        float s0[4], s1[3][4], s2[9][4];
        *(float4*)s0 = __ldg((const float4*)&up[0]);
        #pragma unroll
        for (int i = 0; i < 3; i++) *(float4*)s1[i] = __ldg((const float4*)&up[(1 + i) * CC]);
        #pragma unroll
        for (int q = 0; q < 9; q++) *(float4*)s2[q] = __ldg((const float4*)&up[(4 + q) * CC]);

        float av[13];
        #pragma unroll
        for (int k = 0; k < 13; k++) av[k] = s_a[e * 16 + k];
        const float  a0v = av[0];
        const float* a1v = av + 1;
        const float* a2v = av + 4;

        float w[NPATHS][4];
        #pragma unroll
        for (int p = 0; p < NPATHS; p++)
            *(float4*)w[p] = *(const float4*)&s_w[e * PS + p * CC + c0];

        float* __restrict__ ap = &g_acc[dst * NCOMP * CC + c0];

        float o0[4];
        #pragma unroll
        for (int c = 0; c < 4; c++) {
            float dot11 = a1v[0]*s1[0][c] + a1v[1]*s1[1][c] + a1v[2]*s1[2][c];
            float dot22 = 0.f;
            #pragma unroll
            for (int q = 0; q < 9; q++) dot22 = fmaf(a2v[q], s2[q][c], dot22);
            o0[c] = w[0][c] * (a0v * s0[c]) + w[1][c] * dot11 + w[2][c] * dot22;
        }
        red4(ap, o0[0], o0[1], o0[2], o0[3]);

        #pragma unroll
        for (int i = 0; i < 3; i++) {
            float o1[4];
            #pragma unroll
            for (int c = 0; c < 4; c++) {
                float m21 = 0.f, m12 = 0.f;
                #pragma unroll
                for (int j = 0; j < 3; j++) {
                    m21 = fmaf(a2v[i*3 + j], s1[j][c], m21);
                    m12 = fmaf(a1v[j], s2[i*3 + j][c], m12);
                }
                o1[c] = w[3][c]*(a1v[i]*s0[c]) + w[4][c]*(a0v*s1[i][c]) + w[5][c]*m21 + w[6][c]*m12;
            }
            red4(ap + (1 + i) * CC, o1[0], o1[1], o1[2], o1[3]);
        }

        #pragma unroll
        for (int i = 0; i < 3; i++) {
            #pragma unroll
            for (int j = 0; j < 3; j++) {
                float o2[4];
                #pragma unroll
                for (int c = 0; c < 4; c++) {
                    float mm = 0.f;
                    #pragma unroll
                    for (int kk = 0; kk < 3; kk++)
                        mm = fmaf(a2v[i*3 + kk], s2[kk*3 + j][c], mm);
                    o2[c] = w[7][c]*(a1v[i]*s1[j][c]) + w[8][c]*(a2v[i*3+j]*s0[c])
                          + w[9][c]*(a0v*s2[i*3+j][c]) + w[10][c]*mm;
                }
                red4(ap + (4 + i*3 + j) * CC, o2[0], o2[1], o2[2], o2[3]);
            }
        }
    }
}

// ---------------------------------------------------------------------------
__global__ void k_final(const float* __restrict__ D0, const float* __restrict__ D1,
                        const float* __restrict__ D2, float* __restrict__ out, int N)
{
    int idx = blockIdx.x * blockDim.x + threadIdx.x;
    if (idx >= N * CC) return;
    const int n = idx >> 6, c = idx & 63;
    const float inv = 1.0f / 32.0f;
    const float* __restrict__ ap = &g_acc[n * NCOMP * CC + c];

    float m0 = ap[0] * inv;
    float m1[3], m2[9];
    #pragma unroll
    for (int i = 0; i < 3; i++) m1[i] = ap[(1 + i) * CC] * inv;
    #pragma unroll
    for (int q = 0; q < 9; q++) m2[q] = ap[(4 + q) * CC] * inv;

    out[idx] = m0 * __ldg(&D0[0]);

    float* __restrict__ o1 = out + N * CC;
    #pragma unroll
    for (int j = 0; j < 3; j++) {
        float s = 0.f;
        #pragma unroll
        for (int i = 0; i < 3; i++) s = fmaf(m1[i], __ldg(&D1[i * 3 + j]), s);
        o1[idx * 3 + j] = s;
    }
    float* __restrict__ o2 = out + N * CC * 4;
    #pragma unroll
    for (int q = 0; q < 9; q++) {
        float s = 0.f;
        #pragma unroll
        for (int p = 0; p < 9; p++) s = fmaf(m2[p], __ldg(&D2[p * 9 + q]), s);
        o2[idx * 9 + q] = s;
    }
}

// ---------------------------------------------------------------------------
extern "C" void kernel_launch(void* const* d_in, const int* in_sizes, int n_in,
                              void* d_out, int out_size)
{
    const float* t0  = (const float*)d_in[0];
    const float* t1  = (const float*)d_in[1];
    const float* t2  = (const float*)d_in[2];
    const float* a0  = (const float*)d_in[3];
    const float* a1  = (const float*)d_in[4];
    const float* a2  = (const float*)d_in[5];
    const float* ef  = (const float*)d_in[6];
    const float* cut = (const float*)d_in[7];
    const float* W0  = (const float*)d_in[8];
    const float* W1  = (const float*)d_in[9];
    const float* W2  = (const float*)d_in[10];
    const float* Wr0 = (const float*)d_in[11];
    const float* Wr1 = (const float*)d_in[12];
    const float* Wr2 = (const float*)d_in[13];
    const float* Wr3 = (const float*)d_in[14];
    const float* D0  = (const float*)d_in[15];
    const float* D1  = (const float*)d_in[16];
    const float* D2  = (const float*)d_in[17];
    const int*   ei  = (const int*)d_in[18];

    const int N = in_sizes[0] / CC;   // 8000
    const int E = in_sizes[3];        // 256000
    float* out = (float*)d_out;

    cudaFuncSetAttribute(k_mlp,   cudaFuncAttributeMaxDynamicSharedMemorySize, M_SMEM);
    cudaFuncSetAttribute(k_fused, cudaFuncAttributeMaxDynamicSharedMemorySize, F_SMEM);

    const int n4 = (N * NCOMP * CC) / 4;
    k_zero<<<(n4 + 255) / 256, 256>>>(n4);
    k_cvtw<<<(13440 + 255) / 256, 256>>>(Wr0, Wr1, Wr2, Wr3);
    k_linear_up<<<N, 128>>>(t0, t1, t2, W0, W1, W2);
    k_mlp<<<(E + MEPB - 1) / MEPB, 256, M_SMEM>>>(ef, E);
    k_fused<<<(E + FEPB - 1) / FEPB, 256, F_SMEM>>>(a0, a1, a2, cut, ei, E);
    k_final<<<(N * CC + 255) / 256, 256>>>(D0, D1, D2, out, N);
}